// round 10
// baseline (speedup 1.0000x reference)
#include <cuda_runtime.h>

// ---------------- problem constants ----------------
#define BB    2
#define SS    16
#define NN    5000
#define HH    64
#define EE    20000
#define BSS   (BB*SS)      // 32
#define BNN   (BB*NN)      // 10000
#define NROWS (BSS*NN)     // 160000

// ---------------- scratch (device globals) ----------------
__device__ __align__(16) float g_x1[NROWS*HH];
__device__ __align__(16) float g_x2[NROWS*HH];
__device__ __align__(16) float g_P [NROWS*128];
__device__ __align__(16) float g_Q [NROWS*128];
__device__ __align__(16) float g_R [EE*128];
__device__ __align__(16) float g_G [NROWS*128];
__device__ int  g_cnt[NN];
__device__ int  g_cur[NN];
__device__ int  g_off[NN+1];
__device__ int2 g_epk[EE];     // (src, e) sorted by dst

// fragment-permuted weights (filled once per launch by prep_kernel)
__device__ __align__(16) float g_Wif [12288];   // in_proj 64x192, NT=24
__device__ __align__(16) float g_Wof [4096];    // out_proj 64x64, NT=8
__device__ __align__(16) float g_Wpqf[16384];   // [Wa-Wb | Wb] 64x256, NT=32
__device__ __align__(16) float g_W2f [8192];    // mw2 128x64, NT=8
__device__ __align__(16) float g_U1f [8192];    // uw1 128x64, NT=8
__device__ __align__(16) float g_U2f [4096];    // uw2 64x64, NT=8
__device__ __align__(16) float g_F1f [16384];   // fw1 64x256, NT=32
__device__ __align__(16) float g_F2f [16384];   // fw2 256x64, NT=8

__device__ __forceinline__ float gelu_f(float v) {
    return 0.5f * v * (1.0f + erff(v * 0.70710678118654752f));
}

__device__ __forceinline__ float to_tf32(float x) {
    unsigned r;
    asm("cvt.rna.tf32.f32 %0, %1;" : "=r"(r) : "f"(x));
    return __uint_as_float(r);
}

__device__ __forceinline__ int fragidx(int k, int c, int NT) {
    int kt = k >> 3, kk = k & 7, j = kk >> 2, tg = kk & 3;
    int nt = c >> 3, gg = c & 7;
    return ((kt*NT + nt)*32 + (gg<<2) + tg)*2 + j;
}

// mma.m16n8k8 tf32: D(16x8) += A(16x8,row) * B(8x8,col)
__device__ __forceinline__ void mma_tf32(float4& d,
    float a0, float a1, float a2, float a3, float b0, float b1)
{
    asm volatile(
      "mma.sync.aligned.m16n8k8.row.col.f32.tf32.tf32.f32 "
      "{%0,%1,%2,%3},{%4,%5,%6,%7},{%8,%9},{%0,%1,%2,%3};\n"
      : "+f"(d.x), "+f"(d.y), "+f"(d.z), "+f"(d.w)
      : "r"(__float_as_uint(a0)), "r"(__float_as_uint(a1)),
        "r"(__float_as_uint(a2)), "r"(__float_as_uint(a3)),
        "r"(__float_as_uint(b0)), "r"(__float_as_uint(b1)));
}

// ---------------- prep: permute weights + zero CSR counters -----------------
__global__ void prep_kernel(
    const float* __restrict__ Wi,  const float* __restrict__ Wo,
    const float* __restrict__ mw1, const float* __restrict__ mw2,
    const float* __restrict__ uw1, const float* __restrict__ uw2,
    const float* __restrict__ fw1, const float* __restrict__ fw2)
{
    int i = blockIdx.x * 512 + threadIdx.x;   // grid 178*512
    if (i < 12288) {                              // Wi 64x192
        int k = i / 192, c = i % 192;
        g_Wif[fragidx(k, c, 24)] = to_tf32(Wi[i]);
    } else if (i < 16384) {                       // Wo 64x64
        int idx = i - 12288, k = idx >> 6, c = idx & 63;
        g_Wof[fragidx(k, c, 8)] = to_tf32(Wo[idx]);
    } else if (i < 32768) {                       // pq combined 64x256
        int idx = i - 16384, k = idx >> 8, c = idx & 255;
        float w = (c < 128) ? (mw1[k*128 + c] - mw1[(64+k)*128 + c])
                            :  mw1[(64+k)*128 + (c-128)];
        g_Wpqf[fragidx(k, c, 32)] = to_tf32(w);
    } else if (i < 40960) {                       // mw2 128x64
        int idx = i - 32768, k = idx >> 6, c = idx & 63;
        g_W2f[fragidx(k, c, 8)] = to_tf32(mw2[idx]);
    } else if (i < 49152) {                       // uw1 128x64
        int idx = i - 40960, k = idx >> 6, c = idx & 63;
        g_U1f[fragidx(k, c, 8)] = to_tf32(uw1[idx]);
    } else if (i < 53248) {                       // uw2 64x64
        int idx = i - 49152, k = idx >> 6, c = idx & 63;
        g_U2f[fragidx(k, c, 8)] = to_tf32(uw2[idx]);
    } else if (i < 69632) {                       // fw1 64x256
        int idx = i - 53248, k = idx >> 8, c = idx & 255;
        g_F1f[fragidx(k, c, 32)] = to_tf32(fw1[idx]);
    } else if (i < 86016) {                       // fw2 256x64
        int idx = i - 69632, k = idx >> 6, c = idx & 63;
        g_F2f[fragidx(k, c, 8)] = to_tf32(fw2[idx]);
    } else if (i < 86016 + NN) {                  // zero CSR counters
        g_cnt[i - 86016] = 0;
    }
}

// ---------------- CSR build ----------------
__global__ void csr_count_kernel(const int* __restrict__ ei) {
    int e = blockIdx.x * blockDim.x + threadIdx.x;
    if (e < EE) atomicAdd(&g_cnt[ei[EE + e]], 1);
}
__global__ void csr_scan_kernel() {
    __shared__ int sbuf[1024];
    __shared__ int scarry;
    int t = threadIdx.x;
    if (t == 0) scarry = 0;
    __syncthreads();
    for (int ch = 0; ch < 5; ch++) {
        int idx = ch * 1024 + t;
        int v = (idx < NN) ? g_cnt[idx] : 0;
        sbuf[t] = v; __syncthreads();
        for (int o = 1; o < 1024; o <<= 1) {
            int x = (t >= o) ? sbuf[t - o] : 0;
            __syncthreads();
            sbuf[t] += x;
            __syncthreads();
        }
        int incl = sbuf[t];
        int base = scarry;
        if (idx < NN) { int off = base + incl - v; g_off[idx] = off; g_cur[idx] = off; }
        __syncthreads();
        if (t == 1023) scarry = base + sbuf[1023];
        __syncthreads();
    }
    if (t == 0) g_off[NN] = scarry;
}
__global__ void csr_fill_kernel(const int* __restrict__ ei) {
    int e = blockIdx.x * blockDim.x + threadIdx.x;
    if (e < EE) {
        int dst = ei[EE + e];
        int pos = atomicAdd(&g_cur[dst], 1);
        g_epk[pos] = make_int2(ei[e], e);
    }
}

// ---------------- K1: temporal attention via tf32 MMA + residual + LN -------
__global__ __launch_bounds__(512, 2) void attn_kernel(
    const float* __restrict__ x,
    const float* __restrict__ bi, const float* __restrict__ bo,
    const float* __restrict__ tg_, const float* __restrict__ tb_)
{
    extern __shared__ float sm[];
    float* sbi  = sm;            // 192
    float* sbo  = sbi + 192;     // 64
    float* stg  = sbo + 64;      // 64
    float* stb  = stg + 64;      // 64
    float* sX   = stb + 64;      // 64x68 tf32 (also residual source)
    float* sqkvT= sX + 4352;     // [seq<4][j<192][s<16] pad20 = 15360
    float* saoT = sqkvT + 15360; // [seq<4][d<64][q<16] pad20 = 5120
    float* sY   = sqkvT;         // alias: sqkvT dead after softmax
    float* smean= saoT + 5120;   // 64
    float* sinv = smean + 64;    // 64

    int t = threadIdx.x;
    if (t < 192) sbi[t] = bi[t];
    if (t < 64) { sbo[t] = bo[t]; stg[t] = tg_[t]; stb[t] = tb_[t]; }

    int bn0 = blockIdx.x * 4;
    for (int idx = t; idx < 4096; idx += 512) {
        int row = idx >> 6, c = idx & 63;
        int seq = row >> 4, s = row & 15;
        int bn = bn0 + seq;
        int b = bn / NN, n = bn % NN;
        sX[row*68 + c] = to_tf32(x[((b*SS + s)*NN + n)*HH + c]);
    }
    __syncthreads();

    int w = t >> 5, lane = t & 31, g = lane >> 2, tg = lane & 3;

    // qkv = X @ Wi + bi : M=64, N=192, K=64. warp: mt=w>>2, 6 n-tiles
    {
        int mt = w >> 2, ng = w & 3;
        float4 d[6];
        #pragma unroll
        for (int i = 0; i < 6; i++) {
            int col = (ng*6 + i)*8 + 2*tg;
            d[i] = make_float4(sbi[col], sbi[col+1], sbi[col], sbi[col+1]);
        }
        #pragma unroll
        for (int kt = 0; kt < 8; kt++) {
            const float* Ab = sX + (mt*16)*68 + kt*8;
            float a0 = Ab[g*68 + tg],     a1 = Ab[(g+8)*68 + tg];
            float a2 = Ab[g*68 + tg + 4], a3 = Ab[(g+8)*68 + tg + 4];
            #pragma unroll
            for (int i = 0; i < 6; i++) {
                int nt = ng*6 + i;
                float2 b = __ldg((const float2*)&g_Wif[((kt*24 + nt)*32 + lane)*2]);
                mma_tf32(d[i], a0, a1, a2, a3, b.x, b.y);
            }
        }
        #pragma unroll
        for (int i = 0; i < 6; i++) {
            int col = (ng*6 + i)*8 + 2*tg;
            float* base = sqkvT + (mt*192 + col)*20;
            base[g]        = d[i].x;
            base[20 + g]   = d[i].y;
            base[g + 8]    = d[i].z;
            base[20 + g+8] = d[i].w;
        }
    }
    __syncthreads();

    // attention core (exact fp32): thread = (seq, head, q), 256 active
    if (t < 256) {
        int seq = t >> 6, h = (t >> 4) & 3, q = t & 15;
        const float* Qb = sqkvT + (seq*192 + h*16)*20;
        const float* Kb = Qb + 64*20;
        const float* Vb = Qb + 128*20;
        float sc[16];
        #pragma unroll
        for (int k = 0; k < 16; k++) sc[k] = 0.f;
        #pragma unroll
        for (int d = 0; d < 16; d++) {
            float qv = Qb[d*20 + q];
            const float4* kk = (const float4*)(Kb + d*20);
            float4 k0 = kk[0], k1 = kk[1], k2 = kk[2], k3 = kk[3];
            sc[0]+=qv*k0.x; sc[1]+=qv*k0.y; sc[2]+=qv*k0.z; sc[3]+=qv*k0.w;
            sc[4]+=qv*k1.x; sc[5]+=qv*k1.y; sc[6]+=qv*k1.z; sc[7]+=qv*k1.w;
            sc[8]+=qv*k2.x; sc[9]+=qv*k2.y; sc[10]+=qv*k2.z; sc[11]+=qv*k2.w;
            sc[12]+=qv*k3.x; sc[13]+=qv*k3.y; sc[14]+=qv*k3.z; sc[15]+=qv*k3.w;
        }
        float mx = -1e30f;
        #pragma unroll
        for (int k = 0; k < 16; k++) { sc[k] *= 0.25f; mx = fmaxf(mx, sc[k]); }
        float den = 0.f;
        #pragma unroll
        for (int k = 0; k < 16; k++) { sc[k] = expf(sc[k] - mx); den += sc[k]; }
        float inv = 1.f / den;
        #pragma unroll
        for (int d = 0; d < 16; d++) {
            const float4* vv = (const float4*)(Vb + d*20);
            float4 v0 = vv[0], v1 = vv[1], v2 = vv[2], v3 = vv[3];
            float o = sc[0]*v0.x + sc[1]*v0.y + sc[2]*v0.z + sc[3]*v0.w
                    + sc[4]*v1.x + sc[5]*v1.y + sc[6]*v1.z + sc[7]*v1.w
                    + sc[8]*v2.x + sc[9]*v2.y + sc[10]*v2.z + sc[11]*v2.w
                    + sc[12]*v3.x + sc[13]*v3.y + sc[14]*v3.z + sc[15]*v3.w;
            saoT[(seq*64 + h*16 + d)*20 + q] = to_tf32(o * inv);
        }
    }
    __syncthreads();

    // out-proj: Y = X + AO @ Wo + bo
    {
        int mt = w >> 2, np = w & 3;
        float4 d[2];
        #pragma unroll
        for (int i = 0; i < 2; i++) {
            int col = (np*2 + i)*8 + 2*tg;
            d[i] = make_float4(sbo[col], sbo[col+1], sbo[col], sbo[col+1]);
        }
        #pragma unroll
        for (int kt = 0; kt < 8; kt++) {
            const float* Ab = saoT + (mt*64 + kt*8)*20;
            float a0 = Ab[tg*20 + g],       a1 = Ab[tg*20 + g + 8];
            float a2 = Ab[(tg+4)*20 + g],   a3 = Ab[(tg+4)*20 + g + 8];
            #pragma unroll
            for (int i = 0; i < 2; i++) {
                int nt = np*2 + i;
                float2 b = __ldg((const float2*)&g_Wof[((((kt<<3) + nt)<<5) + lane)*2]);
                mma_tf32(d[i], a0, a1, a2, a3, b.x, b.y);
            }
        }
        int r0 = mt*16 + g;
        #pragma unroll
        for (int i = 0; i < 2; i++) {
            int col = (np*2 + i)*8 + 2*tg;
            sY[r0*64 + col]       = sX[r0*68 + col]       + d[i].x;
            sY[r0*64 + col+1]     = sX[r0*68 + col+1]     + d[i].y;
            sY[(r0+8)*64 + col]   = sX[(r0+8)*68 + col]   + d[i].z;
            sY[(r0+8)*64 + col+1] = sX[(r0+8)*68 + col+1] + d[i].w;
        }
    }
    __syncthreads();

    // LN: 64 rows, 8 lanes per row
    {
        int r = t >> 3, l = t & 7;
        float4 v1 = *(const float4*)&sY[r*64 + l*8];
        float4 v2 = *(const float4*)&sY[r*64 + l*8 + 4];
        float s  = v1.x+v1.y+v1.z+v1.w + v2.x+v2.y+v2.z+v2.w;
        float ss = v1.x*v1.x+v1.y*v1.y+v1.z*v1.z+v1.w*v1.w
                 + v2.x*v2.x+v2.y*v2.y+v2.z*v2.z+v2.w*v2.w;
        #pragma unroll
        for (int o = 1; o < 8; o <<= 1) {
            s  += __shfl_xor_sync(0xffffffffu, s,  o, 8);
            ss += __shfl_xor_sync(0xffffffffu, ss, o, 8);
        }
        if (l == 0) {
            float m = s * (1.f/64.f);
            float var = ss * (1.f/64.f) - m*m;
            smean[r] = m; sinv[r] = rsqrtf(var + 1e-5f);
        }
    }
    __syncthreads();
    for (int idx = t; idx < 4096; idx += 512) {
        int row = idx >> 6, c = idx & 63;
        int seq = row >> 4, s = row & 15;
        int bn = bn0 + seq;
        int b = bn / NN, n = bn % NN;
        g_x1[((b*SS + s)*NN + n)*HH + c] =
            (sY[idx] - smean[row]) * sinv[row] * stg[c] + stb[c];
    }
}

// ---------------- K2: edge embedding -> R ---------------------
__global__ void edge_emb_kernel(const float* __restrict__ ea,
                                const float* __restrict__ ew1, const float* __restrict__ eb1,
                                const float* __restrict__ ew2, const float* __restrict__ eb2,
                                const float* __restrict__ mw1, const float* __restrict__ mb1)
{
    extern __shared__ float sm[];
    float* sEw2 = sm;            // 64*64
    float* sWc  = sEw2 + 4096;   // 64*128
    float* sew1 = sWc + 8192;
    float* seb1 = sew1 + 64;
    float* seb2 = seb1 + 64;
    float* smb1 = seb2 + 64;     // 128
    float* semb = smb1 + 128;    // 64
    float* semb2= semb + 64;     // 64

    int t = threadIdx.x;   // 128
    for (int i = t; i < 4096; i += 128) sEw2[i] = ew2[i];
    for (int i = t; i < 8192; i += 128) sWc[i]  = mw1[128*128 + i];
    if (t < 64) { sew1[t] = ew1[t]; seb1[t] = eb1[t]; seb2[t] = eb2[t]; }
    smb1[t] = mb1[t];
    __syncthreads();

    for (int e = blockIdx.x; e < EE; e += gridDim.x) {
        if (t < 64) semb[t] = gelu_f(ea[e] * sew1[t] + seb1[t]);
        __syncthreads();
        if (t < 64) {
            float a = seb2[t];
            #pragma unroll 8
            for (int i = 0; i < 64; i++) a += semb[i] * sEw2[i*64 + t];
            semb2[t] = a;
        }
        __syncthreads();
        {
            float a = smb1[t];
            #pragma unroll 8
            for (int i = 0; i < 64; i++) a += semb2[i] * sWc[i*128 + t];
            g_R[e*128 + t] = a;
        }
        __syncthreads();
    }
}

// ---------------- K3: P,Q node GEMM via tf32 MMA (weights from gmem) --------
__global__ __launch_bounds__(512) void pq_kernel()
{
    extern __shared__ float sm[];
    float* sA = sm;   // 32 x 68 (tf32)

    int t = threadIdx.x;
    int rbase = blockIdx.x * 32;
    for (int idx = t; idx < 2048; idx += 512) {
        int r = idx >> 6, c = idx & 63;
        sA[r*68 + c] = to_tf32(g_x1[(rbase + r)*64 + c]);
    }
    __syncthreads();

    int w = t >> 5, lane = t & 31, g = lane >> 2, tg = lane & 3;
    int mt = w >> 3, ng = w & 7;
    float4 d[4];
    #pragma unroll
    for (int i = 0; i < 4; i++) d[i] = make_float4(0.f, 0.f, 0.f, 0.f);

    #pragma unroll
    for (int kt = 0; kt < 8; kt++) {
        const float* Ab = sA + (mt*16)*68 + kt*8;
        float a0 = Ab[g*68 + tg],     a1 = Ab[(g+8)*68 + tg];
        float a2 = Ab[g*68 + tg + 4], a3 = Ab[(g+8)*68 + tg + 4];
        #pragma unroll
        for (int i = 0; i < 4; i++) {
            int nt = ng*4 + i;
            float2 b = __ldg((const float2*)&g_Wpqf[((((kt<<5) + nt)<<5) + lane)*2]);
            mma_tf32(d[i], a0, a1, a2, a3, b.x, b.y);
        }
    }

    #pragma unroll
    for (int i = 0; i < 4; i++) {
        int nt = ng*4 + i;
        int col = nt*8 + 2*tg;
        float* base = (col < 128) ? (g_P + rbase*128 + col)
                                  : (g_Q + rbase*128 + (col - 128));
        int r0 = mt*16 + g;
        *(float2*)&base[r0*128]     = make_float2(d[i].x, d[i].y);
        *(float2*)&base[(r0+8)*128] = make_float2(d[i].z, d[i].w);
    }
}

// ---------------- K4: CSR gather aggregation -------------------------------
// block = dst (grid 5000), warp = 4 batch-slices -> R row loaded once per
// warp (L1-broadcast across the block's 8 warps), 5 independent loads/edge.
__global__ __launch_bounds__(256) void aggr_kernel()
{
    int dst = blockIdx.x;
    int wid = threadIdx.x >> 5;      // 0..7
    int lane = threadIdx.x & 31;
    int bs0 = wid * 4;

    const float4* P4 = (const float4*)g_P;
    const float4* Q4 = (const float4*)g_Q;
    const float4* R4 = (const float4*)g_R;

    float4 q[4], acc[4];
    #pragma unroll
    for (int j = 0; j < 4; j++) {
        q[j] = __ldg(Q4 + ((bs0 + j)*NN + dst)*32 + lane);
        acc[j] = make_float4(0.f, 0.f, 0.f, 0.f);
    }

    int s = __ldg(&g_off[dst]), e = __ldg(&g_off[dst+1]);
    if (s < e) {
        int2 pe = __ldg(&g_epk[s]);
        for (int k = s; k < e; k++) {
            int2 pen = (k + 1 < e) ? __ldg(&g_epk[k+1]) : pe;
            float4 r = __ldg(R4 + pe.y*32 + lane);
            float4 p[4];
            #pragma unroll
            for (int j = 0; j < 4; j++)
                p[j] = __ldg(P4 + ((bs0 + j)*NN + pe.x)*32 + lane);
            #pragma unroll
            for (int j = 0; j < 4; j++) {
                acc[j].x += gelu_f(p[j].x + q[j].x + r.x);
                acc[j].y += gelu_f(p[j].y + q[j].y + r.y);
                acc[j].z += gelu_f(p[j].z + q[j].z + r.z);
                acc[j].w += gelu_f(p[j].w + q[j].w + r.w);
            }
            pe = pen;
        }
    }
    #pragma unroll
    for (int j = 0; j < 4; j++)
        ((float4*)g_G)[((bs0 + j)*NN + dst)*32 + lane] = acc[j];
}

// ---------------- K5: update MLP via tf32 MMA + residual + LN ----------------
__global__ __launch_bounds__(512) void update_kernel(
    const float* __restrict__ mb2, const float* __restrict__ ub1,
    const float* __restrict__ ub2,
    const float* __restrict__ sg,  const float* __restrict__ sb)
{
    extern __shared__ float sm[];
    float* sG   = sm;               // 32 x 132 tf32
    float* sUin = sG + 4224;        // 32 x 132 tf32
    float* sHid = sUin + 4224;      // 32 x 68 tf32
    float* sXr  = sHid + 2176;      // 32 x 64 fp32
    float* sY   = sXr + 2048;       // 32 x 64
    float* smb2 = sY + 2048;        // 64
    float* sub1 = smb2 + 64;
    float* sub2 = sub1 + 64;
    float* ssg  = sub2 + 64;
    float* ssb  = ssg + 64;
    float* sdeg = ssb + 64;         // 32
    float* smean= sdeg + 32;        // 32
    float* sinv = smean + 32;       // 32

    int t = threadIdx.x;
    if (t < 64) { smb2[t] = mb2[t]; sub1[t] = ub1[t]; sub2[t] = ub2[t]; ssg[t] = sg[t]; ssb[t] = sb[t]; }

    int rbase = blockIdx.x * 32;
    for (int idx = t; idx < 4096; idx += 512) {
        int c = idx & 127, r = idx >> 7;
        sG[r*132 + c] = to_tf32(g_G[(rbase + r)*128 + c]);
    }
    for (int idx = t; idx < 2048; idx += 512) {
        int c = idx & 63, r = idx >> 6;
        float v = g_x1[(rbase + r)*64 + c];
        sXr[r*64 + c] = v;
        sUin[r*132 + c] = to_tf32(v);
    }
    if (t < 32) {
        int n = (rbase + t) % NN;
        sdeg[t] = (float)(g_off[n+1] - g_off[n]);
    }
    __syncthreads();

    int w = t >> 5, lane = t & 31, g = lane >> 2, tg = lane & 3;
    int mt = w >> 3, nt = w & 7;
    int col = nt*8 + 2*tg;
    int r0 = mt*16 + g;

    // Stage0: aggr = G @ mw2 + deg*mb2
    {
        float4 d = make_float4(sdeg[r0]*smb2[col],   sdeg[r0]*smb2[col+1],
                               sdeg[r0+8]*smb2[col], sdeg[r0+8]*smb2[col+1]);
        #pragma unroll
        for (int kt = 0; kt < 16; kt++) {
            const float* Ab = sG + (mt*16)*132 + kt*8;
            float a0 = Ab[g*132 + tg],     a1 = Ab[(g+8)*132 + tg];
            float a2 = Ab[g*132 + tg + 4], a3 = Ab[(g+8)*132 + tg + 4];
            float2 b = __ldg((const float2*)&g_W2f[((((kt<<3) + nt)<<5) + lane)*2]);
            mma_tf32(d, a0, a1, a2, a3, b.x, b.y);
        }
        *(float2*)&sUin[r0*132 + 64 + col]     = make_float2(to_tf32(d.x), to_tf32(d.y));
        *(float2*)&sUin[(r0+8)*132 + 64 + col] = make_float2(to_tf32(d.z), to_tf32(d.w));
    }
    __syncthreads();

    // Stage1: hid = gelu(Uin @ uw1 + ub1)
    {
        float4 d = make_float4(sub1[col], sub1[col+1], sub1[col], sub1[col+1]);
        #pragma unroll
        for (int kt = 0; kt < 16; kt++) {
            const float* Ab = sUin + (mt*16)*132 + kt*8;
            float a0 = Ab[g*132 + tg],     a1 = Ab[(g+8)*132 + tg];
            float a2 = Ab[g*132 + tg + 4], a3 = Ab[(g+8)*132 + tg + 4];
            float2 b = __ldg((const float2*)&g_U1f[((((kt<<3) + nt)<<5) + lane)*2]);
            mma_tf32(d, a0, a1, a2, a3, b.x, b.y);
        }
        *(float2*)&sHid[r0*68 + col]     = make_float2(to_tf32(gelu_f(d.x)), to_tf32(gelu_f(d.y)));
        *(float2*)&sHid[(r0+8)*68 + col] = make_float2(to_tf32(gelu_f(d.z)), to_tf32(gelu_f(d.w)));
    }
    __syncthreads();

    // Stage2: y = xs + hid @ uw2 + ub2
    {
        float4 d = make_float4(sub2[col], sub2[col+1], sub2[col], sub2[col+1]);
        #pragma unroll
        for (int kt = 0; kt < 8; kt++) {
            const float* Ab = sHid + (mt*16)*68 + kt*8;
            float a0 = Ab[g*68 + tg],     a1 = Ab[(g+8)*68 + tg];
            float a2 = Ab[g*68 + tg + 4], a3 = Ab[(g+8)*68 + tg + 4];
            float2 b = __ldg((const float2*)&g_U2f[((((kt<<3) + nt)<<5) + lane)*2]);
            mma_tf32(d, a0, a1, a2, a3, b.x, b.y);
        }
        sY[r0*64 + col]       = sXr[r0*64 + col]       + d.x;
        sY[r0*64 + col+1]     = sXr[r0*64 + col+1]     + d.y;
        sY[(r0+8)*64 + col]   = sXr[(r0+8)*64 + col]   + d.z;
        sY[(r0+8)*64 + col+1] = sXr[(r0+8)*64 + col+1] + d.w;
    }
    __syncthreads();

    // LN
    {
        int r = t >> 4, l = t & 15;
        float4 v = *(const float4*)&sY[r*64 + l*4];
        float s  = v.x + v.y + v.z + v.w;
        float ss = v.x*v.x + v.y*v.y + v.z*v.z + v.w*v.w;
        #pragma unroll
        for (int o = 1; o < 16; o <<= 1) {
            s  += __shfl_xor_sync(0xffffffffu, s,  o, 16);
            ss += __shfl_xor_sync(0xffffffffu, ss, o, 16);
        }
        if (l == 0) {
            float m = s * (1.f/64.f);
            float var = ss * (1.f/64.f) - m*m;
            smean[r] = m; sinv[r] = rsqrtf(var + 1e-5f);
        }
    }
    __syncthreads();
    for (int i = t; i < 2048; i += 512) {
        int r = i >> 6, cc = i & 63;
        g_x2[(rbase + r)*64 + cc] = (sY[i] - smean[r]) * sinv[r] * ssg[cc] + ssb[cc];
    }
}

// ---------------- K6: FFN via tf32 MMA + residual + LN -> d_out --------------
__global__ __launch_bounds__(512) void ffn_kernel(
    const float* __restrict__ fb1, const float* __restrict__ fb2,
    const float* __restrict__ fg,  const float* __restrict__ fb,
    float* __restrict__ out)
{
    extern __shared__ float sm[];
    float* sA   = sm;               // X 32 x 68 tf32
    float* sH   = sA + 2176;        // H 32 x 260 tf32
    float* sXr  = sH + 8320;        // 32 x 64 fp32
    float* sY   = sXr + 2048;       // 32 x 64
    float* sb1  = sY + 2048;        // 256
    float* sb2  = sb1 + 256;        // 64
    float* sfg  = sb2 + 64;
    float* sfb  = sfg + 64;
    float* smean= sfb + 64;         // 32
    float* sinv = smean + 32;       // 32

    int t = threadIdx.x;
    if (t < 256) sb1[t] = fb1[t];
    if (t < 64) { sb2[t] = fb2[t]; sfg[t] = fg[t]; sfb[t] = fb[t]; }

    int rbase = blockIdx.x * 32;
    for (int idx = t; idx < 2048; idx += 512) {
        int c = idx & 63, r = idx >> 6;
        float v = g_x2[(rbase + r)*64 + c];
        sXr[r*64 + c] = v;
        sA[r*68 + c] = to_tf32(v);
    }
    __syncthreads();

    int w = t >> 5, lane = t & 31, g = lane >> 2, tg = lane & 3;

    // Stage1: H = gelu(X @ W1 + b1)
    {
        int mt = w >> 3, ng = w & 7;
        float4 d[4];
        #pragma unroll
        for (int i = 0; i < 4; i++) {
            int col = (ng*4 + i)*8 + 2*tg;
            d[i] = make_float4(sb1[col], sb1[col+1], sb1[col], sb1[col+1]);
        }
        #pragma unroll
        for (int kt = 0; kt < 8; kt++) {
            const float* Ab = sA + (mt*16)*68 + kt*8;
            float a0 = Ab[g*68 + tg],     a1 = Ab[(g+8)*68 + tg];
            float a2 = Ab[g*68 + tg + 4], a3 = Ab[(g+8)*68 + tg + 4];
            #pragma unroll
            for (int i = 0; i < 4; i++) {
                int nt = ng*4 + i;
                float2 b = __ldg((const float2*)&g_F1f[((((kt<<5) + nt)<<5) + lane)*2]);
                mma_tf32(d[i], a0, a1, a2, a3, b.x, b.y);
            }
        }
        int r0 = mt*16 + g;
        #pragma unroll
        for (int i = 0; i < 4; i++) {
            int col = (ng*4 + i)*8 + 2*tg;
            *(float2*)&sH[r0*260 + col]     = make_float2(to_tf32(gelu_f(d[i].x)), to_tf32(gelu_f(d[i].y)));
            *(float2*)&sH[(r0+8)*260 + col] = make_float2(to_tf32(gelu_f(d[i].z)), to_tf32(gelu_f(d[i].w)));
        }
    }
    __syncthreads();

    // Stage2: Y = X + H @ W2 + b2
    {
        int mt = w >> 3, nt = w & 7;
        int col = nt*8 + 2*tg;
        int r0 = mt*16 + g;
        float4 d = make_float4(sb2[col], sb2[col+1], sb2[col], sb2[col+1]);
        #pragma unroll
        for (int kt = 0; kt < 32; kt++) {
            const float* Ab = sH + (mt*16)*260 + kt*8;
            float a0 = Ab[g*260 + tg],     a1 = Ab[(g+8)*260 + tg];
            float a2 = Ab[g*260 + tg + 4], a3 = Ab[(g+8)*260 + tg + 4];
            float2 b = __ldg((const float2*)&g_F2f[((((kt<<3) + nt)<<5) + lane)*2]);
            mma_tf32(d, a0, a1, a2, a3, b.x, b.y);
        }
        sY[r0*64 + col]       = sXr[r0*64 + col]       + d.x;
        sY[r0*64 + col+1]     = sXr[r0*64 + col+1]     + d.y;
        sY[(r0+8)*64 + col]   = sXr[(r0+8)*64 + col]   + d.z;
        sY[(r0+8)*64 + col+1] = sXr[(r0+8)*64 + col+1] + d.w;
    }
    __syncthreads();

    // LN
    {
        int r = t >> 4, l = t & 15;
        float4 v = *(const float4*)&sY[r*64 + l*4];
        float s  = v.x + v.y + v.z + v.w;
        float ss = v.x*v.x + v.y*v.y + v.z*v.z + v.w*v.w;
        #pragma unroll
        for (int o = 1; o < 16; o <<= 1) {
            s  += __shfl_xor_sync(0xffffffffu, s,  o, 16);
            ss += __shfl_xor_sync(0xffffffffu, ss, o, 16);
        }
        if (l == 0) {
            float m = s * (1.f/64.f);
            float var = ss * (1.f/64.f) - m*m;
            smean[r] = m; sinv[r] = rsqrtf(var + 1e-5f);
        }
    }
    __syncthreads();
    for (int i = t; i < 2048; i += 512) {
        int r = i >> 6, cc = i & 63;
        out[(rbase + r)*64 + cc] = (sY[i] - smean[r]) * sinv[r] * sfg[cc] + sfb[cc];
    }
}

// ---------------- host launcher ---------------------------------------------
extern "C" void kernel_launch(void* const* d_in, const int* in_sizes, int n_in,
                              void* d_out, int out_size)
{
    (void)in_sizes; (void)n_in; (void)out_size;
    const float* x    = (const float*)d_in[0];
    const int*   ei   = (const int*)  d_in[1];
    const float* ea   = (const float*)d_in[2];
    const float* ipw  = (const float*)d_in[3];
    const float* ipb  = (const float*)d_in[4];
    const float* opw  = (const float*)d_in[5];
    const float* opb  = (const float*)d_in[6];
    const float* tng  = (const float*)d_in[7];
    const float* tnb  = (const float*)d_in[8];
    const float* ew1  = (const float*)d_in[9];
    const float* eb1  = (const float*)d_in[10];
    const float* ew2  = (const float*)d_in[11];
    const float* eb2  = (const float*)d_in[12];
    const float* mw1  = (const float*)d_in[13];
    const float* mb1  = (const float*)d_in[14];
    const float* mw2  = (const float*)d_in[15];
    const float* mb2  = (const float*)d_in[16];
    const float* uw1  = (const float*)d_in[17];
    const float* ub1  = (const float*)d_in[18];
    const float* uw2  = (const float*)d_in[19];
    const float* ub2  = (const float*)d_in[20];
    const float* sng  = (const float*)d_in[21];
    const float* snb  = (const float*)d_in[22];
    const float* fw1  = (const float*)d_in[23];
    const float* fb1  = (const float*)d_in[24];
    const float* fw2  = (const float*)d_in[25];
    const float* fb2  = (const float*)d_in[26];
    const float* fng  = (const float*)d_in[27];
    const float* fnb  = (const float*)d_in[28];
    float* out = (float*)d_out;

    const int SM_ATT = 25344 * 4;   // 101376
    const int SM_EE  = 12736 * 4;
    const int SM_PQ  = 2176 * 4;    // 8704
    const int SM_UPD = 15136 * 4;   // 60544
    const int SM_FFN = 15104 * 4;   // 60416
    cudaFuncSetAttribute(attn_kernel,     cudaFuncAttributeMaxDynamicSharedMemorySize, SM_ATT);
    cudaFuncSetAttribute(edge_emb_kernel, cudaFuncAttributeMaxDynamicSharedMemorySize, SM_EE);
    cudaFuncSetAttribute(pq_kernel,       cudaFuncAttributeMaxDynamicSharedMemorySize, SM_PQ);
    cudaFuncSetAttribute(update_kernel,   cudaFuncAttributeMaxDynamicSharedMemorySize, SM_UPD);
    cudaFuncSetAttribute(ffn_kernel,      cudaFuncAttributeMaxDynamicSharedMemorySize, SM_FFN);

    // position 4 gets captured by ncu -> pq this time
    prep_kernel      <<<178, 512>>>(ipw, opw, mw1, mw2, uw1, uw2, fw1, fw2);
    attn_kernel      <<<2500, 512, SM_ATT>>>(x, ipb, opb, tng, tnb);
    csr_count_kernel <<<79, 256>>>(ei);
    pq_kernel        <<<5000, 512, SM_PQ>>>();
    csr_scan_kernel  <<<1, 1024>>>();
    csr_fill_kernel  <<<79, 256>>>(ei);
    edge_emb_kernel  <<<256, 128, SM_EE>>>(ea, ew1, eb1, ew2, eb2, mw1, mb1);
    aggr_kernel      <<<5000, 256>>>();
    update_kernel    <<<5000, 512, SM_UPD>>>(mb2, ub1, ub2, sng, snb);
    ffn_kernel       <<<5000, 512, SM_FFN>>>(fb1, fb2, fng, fnb, out);
}

// round 11
// speedup vs baseline: 1.1274x; 1.1274x over previous
#include <cuda_runtime.h>

// ---------------- problem constants ----------------
#define BB    2
#define SS    16
#define NN    5000
#define HH    64
#define EE    20000
#define BSS   (BB*SS)      // 32
#define BNN   (BB*NN)      // 10000
#define NROWS (BSS*NN)     // 160000

// ---------------- scratch (device globals) ----------------
__device__ __align__(16) float g_x1[NROWS*HH];
__device__ __align__(16) float g_x2[NROWS*HH];
__device__ __align__(16) float g_P [NROWS*128];
__device__ __align__(16) float g_Q [NROWS*128];
__device__ __align__(16) float g_R [EE*128];
__device__ __align__(16) float g_G [NROWS*128];
__device__ int  g_cnt[NN];
__device__ int  g_cur[NN];
__device__ int  g_off[NN+1];
__device__ int2 g_epk[EE];     // (src, e) sorted by dst

// fragment-permuted weights (filled once per launch by prep_kernel)
__device__ __align__(16) float g_Wif [12288];   // in_proj 64x192, NT=24
__device__ __align__(16) float g_Wof [4096];    // out_proj 64x64, NT=8
__device__ __align__(16) float g_Wpqf[16384];   // [Wa-Wb | Wb] 64x256, NT=32
__device__ __align__(16) float g_W2f [8192];    // mw2 128x64, NT=8
__device__ __align__(16) float g_U1f [8192];    // uw1 128x64, NT=8
__device__ __align__(16) float g_U2f [4096];    // uw2 64x64, NT=8
__device__ __align__(16) float g_F1f [16384];   // fw1 64x256, NT=32
__device__ __align__(16) float g_F2f [16384];   // fw2 256x64, NT=8
__device__ __align__(16) float g_E2f [4096];    // ew2 64x64, NT=8
__device__ __align__(16) float g_Wcf [8192];    // mw1 rows 128..191 (64x128), NT=16

__device__ __forceinline__ float gelu_f(float v) {
    return 0.5f * v * (1.0f + erff(v * 0.70710678118654752f));
}

__device__ __forceinline__ float to_tf32(float x) {
    unsigned r;
    asm("cvt.rna.tf32.f32 %0, %1;" : "=r"(r) : "f"(x));
    return __uint_as_float(r);
}

__device__ __forceinline__ int fragidx(int k, int c, int NT) {
    int kt = k >> 3, kk = k & 7, j = kk >> 2, tg = kk & 3;
    int nt = c >> 3, gg = c & 7;
    return ((kt*NT + nt)*32 + (gg<<2) + tg)*2 + j;
}

// mma.m16n8k8 tf32: D(16x8) += A(16x8,row) * B(8x8,col)
__device__ __forceinline__ void mma_tf32(float4& d,
    float a0, float a1, float a2, float a3, float b0, float b1)
{
    asm volatile(
      "mma.sync.aligned.m16n8k8.row.col.f32.tf32.tf32.f32 "
      "{%0,%1,%2,%3},{%4,%5,%6,%7},{%8,%9},{%0,%1,%2,%3};\n"
      : "+f"(d.x), "+f"(d.y), "+f"(d.z), "+f"(d.w)
      : "r"(__float_as_uint(a0)), "r"(__float_as_uint(a1)),
        "r"(__float_as_uint(a2)), "r"(__float_as_uint(a3)),
        "r"(__float_as_uint(b0)), "r"(__float_as_uint(b1)));
}

// ---------------- prep: permute weights + zero CSR counters -----------------
__global__ void prep_kernel(
    const float* __restrict__ Wi,  const float* __restrict__ Wo,
    const float* __restrict__ mw1, const float* __restrict__ mw2,
    const float* __restrict__ uw1, const float* __restrict__ uw2,
    const float* __restrict__ fw1, const float* __restrict__ fw2,
    const float* __restrict__ ew2)
{
    int i = blockIdx.x * 512 + threadIdx.x;   // grid 202*512
    if (i < 12288) {                              // Wi 64x192
        int k = i / 192, c = i % 192;
        g_Wif[fragidx(k, c, 24)] = to_tf32(Wi[i]);
    } else if (i < 16384) {                       // Wo 64x64
        int idx = i - 12288, k = idx >> 6, c = idx & 63;
        g_Wof[fragidx(k, c, 8)] = to_tf32(Wo[idx]);
    } else if (i < 32768) {                       // pq combined 64x256
        int idx = i - 16384, k = idx >> 8, c = idx & 255;
        float w = (c < 128) ? (mw1[k*128 + c] - mw1[(64+k)*128 + c])
                            :  mw1[(64+k)*128 + (c-128)];
        g_Wpqf[fragidx(k, c, 32)] = to_tf32(w);
    } else if (i < 40960) {                       // mw2 128x64
        int idx = i - 32768, k = idx >> 6, c = idx & 63;
        g_W2f[fragidx(k, c, 8)] = to_tf32(mw2[idx]);
    } else if (i < 49152) {                       // uw1 128x64
        int idx = i - 40960, k = idx >> 6, c = idx & 63;
        g_U1f[fragidx(k, c, 8)] = to_tf32(uw1[idx]);
    } else if (i < 53248) {                       // uw2 64x64
        int idx = i - 49152, k = idx >> 6, c = idx & 63;
        g_U2f[fragidx(k, c, 8)] = to_tf32(uw2[idx]);
    } else if (i < 69632) {                       // fw1 64x256
        int idx = i - 53248, k = idx >> 8, c = idx & 255;
        g_F1f[fragidx(k, c, 32)] = to_tf32(fw1[idx]);
    } else if (i < 86016) {                       // fw2 256x64
        int idx = i - 69632, k = idx >> 6, c = idx & 63;
        g_F2f[fragidx(k, c, 8)] = to_tf32(fw2[idx]);
    } else if (i < 90112) {                       // ew2 64x64
        int idx = i - 86016, k = idx >> 6, c = idx & 63;
        g_E2f[fragidx(k, c, 8)] = to_tf32(ew2[idx]);
    } else if (i < 98304) {                       // Wc = mw1 rows 128..191, 64x128
        int idx = i - 90112, k = idx >> 7, c = idx & 127;
        g_Wcf[fragidx(k, c, 16)] = to_tf32(mw1[(128 + k)*128 + c]);
    } else if (i < 98304 + NN) {                  // zero CSR counters
        g_cnt[i - 98304] = 0;
    }
}

// ---------------- CSR build ----------------
__global__ void csr_count_kernel(const int* __restrict__ ei) {
    int e = blockIdx.x * blockDim.x + threadIdx.x;
    if (e < EE) atomicAdd(&g_cnt[ei[EE + e]], 1);
}
__global__ void csr_scan_kernel() {
    __shared__ int sbuf[1024];
    __shared__ int scarry;
    int t = threadIdx.x;
    if (t == 0) scarry = 0;
    __syncthreads();
    for (int ch = 0; ch < 5; ch++) {
        int idx = ch * 1024 + t;
        int v = (idx < NN) ? g_cnt[idx] : 0;
        sbuf[t] = v; __syncthreads();
        for (int o = 1; o < 1024; o <<= 1) {
            int x = (t >= o) ? sbuf[t - o] : 0;
            __syncthreads();
            sbuf[t] += x;
            __syncthreads();
        }
        int incl = sbuf[t];
        int base = scarry;
        if (idx < NN) { int off = base + incl - v; g_off[idx] = off; g_cur[idx] = off; }
        __syncthreads();
        if (t == 1023) scarry = base + sbuf[1023];
        __syncthreads();
    }
    if (t == 0) g_off[NN] = scarry;
}
__global__ void csr_fill_kernel(const int* __restrict__ ei) {
    int e = blockIdx.x * blockDim.x + threadIdx.x;
    if (e < EE) {
        int dst = ei[EE + e];
        int pos = atomicAdd(&g_cur[dst], 1);
        g_epk[pos] = make_int2(ei[e], e);
    }
}

// ---------------- K1: temporal attention via tf32 MMA + residual + LN -------
__global__ __launch_bounds__(512, 2) void attn_kernel(
    const float* __restrict__ x,
    const float* __restrict__ bi, const float* __restrict__ bo,
    const float* __restrict__ tg_, const float* __restrict__ tb_)
{
    extern __shared__ float sm[];
    float* sbi  = sm;            // 192
    float* sbo  = sbi + 192;     // 64
    float* stg  = sbo + 64;      // 64
    float* stb  = stg + 64;      // 64
    float* sX   = stb + 64;      // 64x68 tf32 (also residual source)
    float* sqkvT= sX + 4352;     // [seq<4][j<192][s<16] pad20 = 15360
    float* saoT = sqkvT + 15360; // [seq<4][d<64][q<16] pad20 = 5120
    float* sY   = sqkvT;         // alias: sqkvT dead after softmax
    float* smean= saoT + 5120;   // 64
    float* sinv = smean + 64;    // 64

    int t = threadIdx.x;
    if (t < 192) sbi[t] = bi[t];
    if (t < 64) { sbo[t] = bo[t]; stg[t] = tg_[t]; stb[t] = tb_[t]; }

    int bn0 = blockIdx.x * 4;
    for (int idx = t; idx < 4096; idx += 512) {
        int row = idx >> 6, c = idx & 63;
        int seq = row >> 4, s = row & 15;
        int bn = bn0 + seq;
        int b = bn / NN, n = bn % NN;
        sX[row*68 + c] = to_tf32(x[((b*SS + s)*NN + n)*HH + c]);
    }
    __syncthreads();

    int w = t >> 5, lane = t & 31, g = lane >> 2, tg = lane & 3;

    // qkv = X @ Wi + bi : M=64, N=192, K=64. warp: mt=w>>2, 6 n-tiles
    {
        int mt = w >> 2, ng = w & 3;
        float4 d[6];
        #pragma unroll
        for (int i = 0; i < 6; i++) {
            int col = (ng*6 + i)*8 + 2*tg;
            d[i] = make_float4(sbi[col], sbi[col+1], sbi[col], sbi[col+1]);
        }
        #pragma unroll
        for (int kt = 0; kt < 8; kt++) {
            const float* Ab = sX + (mt*16)*68 + kt*8;
            float a0 = Ab[g*68 + tg],     a1 = Ab[(g+8)*68 + tg];
            float a2 = Ab[g*68 + tg + 4], a3 = Ab[(g+8)*68 + tg + 4];
            #pragma unroll
            for (int i = 0; i < 6; i++) {
                int nt = ng*6 + i;
                float2 b = __ldg((const float2*)&g_Wif[((kt*24 + nt)*32 + lane)*2]);
                mma_tf32(d[i], a0, a1, a2, a3, b.x, b.y);
            }
        }
        #pragma unroll
        for (int i = 0; i < 6; i++) {
            int col = (ng*6 + i)*8 + 2*tg;
            float* base = sqkvT + (mt*192 + col)*20;
            base[g]        = d[i].x;
            base[20 + g]   = d[i].y;
            base[g + 8]    = d[i].z;
            base[20 + g+8] = d[i].w;
        }
    }
    __syncthreads();

    // attention core (exact fp32): thread = (seq, head, q), 256 active
    if (t < 256) {
        int seq = t >> 6, h = (t >> 4) & 3, q = t & 15;
        const float* Qb = sqkvT + (seq*192 + h*16)*20;
        const float* Kb = Qb + 64*20;
        const float* Vb = Qb + 128*20;
        float sc[16];
        #pragma unroll
        for (int k = 0; k < 16; k++) sc[k] = 0.f;
        #pragma unroll
        for (int d = 0; d < 16; d++) {
            float qv = Qb[d*20 + q];
            const float4* kk = (const float4*)(Kb + d*20);
            float4 k0 = kk[0], k1 = kk[1], k2 = kk[2], k3 = kk[3];
            sc[0]+=qv*k0.x; sc[1]+=qv*k0.y; sc[2]+=qv*k0.z; sc[3]+=qv*k0.w;
            sc[4]+=qv*k1.x; sc[5]+=qv*k1.y; sc[6]+=qv*k1.z; sc[7]+=qv*k1.w;
            sc[8]+=qv*k2.x; sc[9]+=qv*k2.y; sc[10]+=qv*k2.z; sc[11]+=qv*k2.w;
            sc[12]+=qv*k3.x; sc[13]+=qv*k3.y; sc[14]+=qv*k3.z; sc[15]+=qv*k3.w;
        }
        float mx = -1e30f;
        #pragma unroll
        for (int k = 0; k < 16; k++) { sc[k] *= 0.25f; mx = fmaxf(mx, sc[k]); }
        float den = 0.f;
        #pragma unroll
        for (int k = 0; k < 16; k++) { sc[k] = expf(sc[k] - mx); den += sc[k]; }
        float inv = 1.f / den;
        #pragma unroll
        for (int d = 0; d < 16; d++) {
            const float4* vv = (const float4*)(Vb + d*20);
            float4 v0 = vv[0], v1 = vv[1], v2 = vv[2], v3 = vv[3];
            float o = sc[0]*v0.x + sc[1]*v0.y + sc[2]*v0.z + sc[3]*v0.w
                    + sc[4]*v1.x + sc[5]*v1.y + sc[6]*v1.z + sc[7]*v1.w
                    + sc[8]*v2.x + sc[9]*v2.y + sc[10]*v2.z + sc[11]*v2.w
                    + sc[12]*v3.x + sc[13]*v3.y + sc[14]*v3.z + sc[15]*v3.w;
            saoT[(seq*64 + h*16 + d)*20 + q] = to_tf32(o * inv);
        }
    }
    __syncthreads();

    // out-proj: Y = X + AO @ Wo + bo
    {
        int mt = w >> 2, np = w & 3;
        float4 d[2];
        #pragma unroll
        for (int i = 0; i < 2; i++) {
            int col = (np*2 + i)*8 + 2*tg;
            d[i] = make_float4(sbo[col], sbo[col+1], sbo[col], sbo[col+1]);
        }
        #pragma unroll
        for (int kt = 0; kt < 8; kt++) {
            const float* Ab = saoT + (mt*64 + kt*8)*20;
            float a0 = Ab[tg*20 + g],       a1 = Ab[tg*20 + g + 8];
            float a2 = Ab[(tg+4)*20 + g],   a3 = Ab[(tg+4)*20 + g + 8];
            #pragma unroll
            for (int i = 0; i < 2; i++) {
                int nt = np*2 + i;
                float2 b = __ldg((const float2*)&g_Wof[((((kt<<3) + nt)<<5) + lane)*2]);
                mma_tf32(d[i], a0, a1, a2, a3, b.x, b.y);
            }
        }
        int r0 = mt*16 + g;
        #pragma unroll
        for (int i = 0; i < 2; i++) {
            int col = (np*2 + i)*8 + 2*tg;
            sY[r0*64 + col]       = sX[r0*68 + col]       + d[i].x;
            sY[r0*64 + col+1]     = sX[r0*68 + col+1]     + d[i].y;
            sY[(r0+8)*64 + col]   = sX[(r0+8)*68 + col]   + d[i].z;
            sY[(r0+8)*64 + col+1] = sX[(r0+8)*68 + col+1] + d[i].w;
        }
    }
    __syncthreads();

    // LN: 64 rows, 8 lanes per row
    {
        int r = t >> 3, l = t & 7;
        float4 v1 = *(const float4*)&sY[r*64 + l*8];
        float4 v2 = *(const float4*)&sY[r*64 + l*8 + 4];
        float s  = v1.x+v1.y+v1.z+v1.w + v2.x+v2.y+v2.z+v2.w;
        float ss = v1.x*v1.x+v1.y*v1.y+v1.z*v1.z+v1.w*v1.w
                 + v2.x*v2.x+v2.y*v2.y+v2.z*v2.z+v2.w*v2.w;
        #pragma unroll
        for (int o = 1; o < 8; o <<= 1) {
            s  += __shfl_xor_sync(0xffffffffu, s,  o, 8);
            ss += __shfl_xor_sync(0xffffffffu, ss, o, 8);
        }
        if (l == 0) {
            float m = s * (1.f/64.f);
            float var = ss * (1.f/64.f) - m*m;
            smean[r] = m; sinv[r] = rsqrtf(var + 1e-5f);
        }
    }
    __syncthreads();
    for (int idx = t; idx < 4096; idx += 512) {
        int row = idx >> 6, c = idx & 63;
        int seq = row >> 4, s = row & 15;
        int bn = bn0 + seq;
        int b = bn / NN, n = bn % NN;
        g_x1[((b*SS + s)*NN + n)*HH + c] =
            (sY[idx] - smean[row]) * sinv[row] * stg[c] + stb[c];
    }
}

// ---------------- K2: edge embedding -> R via tf32 MMA ----------------------
// 32 edges per block (grid 625), 512 threads.
__global__ __launch_bounds__(512) void edge_emb_kernel(
    const float* __restrict__ ea,
    const float* __restrict__ ew1, const float* __restrict__ eb1,
    const float* __restrict__ eb2, const float* __restrict__ mb1)
{
    extern __shared__ float sm[];
    float* sE0  = sm;          // 32x68 tf32
    float* sE2  = sm + 2176;   // 32x68 tf32
    float* sew1 = sm + 4352;   // 64
    float* seb1 = sew1 + 64;   // 64
    float* seb2 = seb1 + 64;   // 64
    float* smb1 = seb2 + 64;   // 128

    int t = threadIdx.x;
    if (t < 64) { sew1[t] = ew1[t]; seb1[t] = eb1[t]; seb2[t] = eb2[t]; }
    else if (t < 192) smb1[t-64] = mb1[t-64];
    int e0 = blockIdx.x * 32;
    __syncthreads();

    // Stage0: E0 = gelu(ea * ew1 + eb1) per edge-row
    for (int idx = t; idx < 2048; idx += 512) {
        int r = idx >> 6, c = idx & 63;
        sE0[r*68 + c] = to_tf32(gelu_f(__ldg(&ea[e0 + r]) * sew1[c] + seb1[c]));
    }
    __syncthreads();

    int w = t >> 5, lane = t & 31, g = lane >> 2, tg = lane & 3;

    // Stage1: E2 = E0 @ ew2 + eb2 : M=32, N=64, K=64
    {
        int mt = w >> 3, nt = w & 7;
        int col = nt*8 + 2*tg;
        int r0 = mt*16 + g;
        float4 d = make_float4(seb2[col], seb2[col+1], seb2[col], seb2[col+1]);
        #pragma unroll
        for (int kt = 0; kt < 8; kt++) {
            const float* Ab = sE0 + (mt*16)*68 + kt*8;
            float a0 = Ab[g*68 + tg],     a1 = Ab[(g+8)*68 + tg];
            float a2 = Ab[g*68 + tg + 4], a3 = Ab[(g+8)*68 + tg + 4];
            float2 b = __ldg((const float2*)&g_E2f[((((kt<<3) + nt)<<5) + lane)*2]);
            mma_tf32(d, a0, a1, a2, a3, b.x, b.y);
        }
        *(float2*)&sE2[r0*68 + col]     = make_float2(to_tf32(d.x), to_tf32(d.y));
        *(float2*)&sE2[(r0+8)*68 + col] = make_float2(to_tf32(d.z), to_tf32(d.w));
    }
    __syncthreads();

    // Stage2: R = E2 @ Wc + mb1 : M=32, N=128, K=64 (warp does 2 n-tiles)
    {
        int mt = w >> 3, ng = w & 7;
        float4 d[2];
        #pragma unroll
        for (int i = 0; i < 2; i++) {
            int col = (ng*2 + i)*8 + 2*tg;
            d[i] = make_float4(smb1[col], smb1[col+1], smb1[col], smb1[col+1]);
        }
        #pragma unroll
        for (int kt = 0; kt < 8; kt++) {
            const float* Ab = sE2 + (mt*16)*68 + kt*8;
            float a0 = Ab[g*68 + tg],     a1 = Ab[(g+8)*68 + tg];
            float a2 = Ab[g*68 + tg + 4], a3 = Ab[(g+8)*68 + tg + 4];
            #pragma unroll
            for (int i = 0; i < 2; i++) {
                int nt = ng*2 + i;
                float2 b = __ldg((const float2*)&g_Wcf[((kt*16 + nt)*32 + lane)*2]);
                mma_tf32(d[i], a0, a1, a2, a3, b.x, b.y);
            }
        }
        int r0 = mt*16 + g;
        #pragma unroll
        for (int i = 0; i < 2; i++) {
            int col = (ng*2 + i)*8 + 2*tg;
            *(float2*)&g_R[(e0 + r0)*128 + col]     = make_float2(d[i].x, d[i].y);
            *(float2*)&g_R[(e0 + r0 + 8)*128 + col] = make_float2(d[i].z, d[i].w);
        }
    }
}

// ---------------- K3: P,Q node GEMM via tf32 MMA (weights from gmem) --------
__global__ __launch_bounds__(512) void pq_kernel()
{
    extern __shared__ float sm[];
    float* sA = sm;   // 32 x 68 (tf32)

    int t = threadIdx.x;
    int rbase = blockIdx.x * 32;
    for (int idx = t; idx < 2048; idx += 512) {
        int r = idx >> 6, c = idx & 63;
        sA[r*68 + c] = to_tf32(g_x1[(rbase + r)*64 + c]);
    }
    __syncthreads();

    int w = t >> 5, lane = t & 31, g = lane >> 2, tg = lane & 3;
    int mt = w >> 3, ng = w & 7;
    float4 d[4];
    #pragma unroll
    for (int i = 0; i < 4; i++) d[i] = make_float4(0.f, 0.f, 0.f, 0.f);

    #pragma unroll
    for (int kt = 0; kt < 8; kt++) {
        const float* Ab = sA + (mt*16)*68 + kt*8;
        float a0 = Ab[g*68 + tg],     a1 = Ab[(g+8)*68 + tg];
        float a2 = Ab[g*68 + tg + 4], a3 = Ab[(g+8)*68 + tg + 4];
        #pragma unroll
        for (int i = 0; i < 4; i++) {
            int nt = ng*4 + i;
            float2 b = __ldg((const float2*)&g_Wpqf[((((kt<<5) + nt)<<5) + lane)*2]);
            mma_tf32(d[i], a0, a1, a2, a3, b.x, b.y);
        }
    }

    #pragma unroll
    for (int i = 0; i < 4; i++) {
        int nt = ng*4 + i;
        int col = nt*8 + 2*tg;
        float* base = (col < 128) ? (g_P + rbase*128 + col)
                                  : (g_Q + rbase*128 + (col - 128));
        int r0 = mt*16 + g;
        *(float2*)&base[r0*128]     = make_float2(d[i].x, d[i].y);
        *(float2*)&base[(r0+8)*128] = make_float2(d[i].z, d[i].w);
    }
}

// ---------------- K4: CSR gather aggregation -------------------------------
__global__ __launch_bounds__(256) void aggr_kernel()
{
    int dst = blockIdx.x;
    int wid = threadIdx.x >> 5;      // 0..7
    int lane = threadIdx.x & 31;
    int bs0 = wid * 4;

    const float4* P4 = (const float4*)g_P;
    const float4* Q4 = (const float4*)g_Q;
    const float4* R4 = (const float4*)g_R;

    float4 q[4], acc[4];
    #pragma unroll
    for (int j = 0; j < 4; j++) {
        q[j] = __ldg(Q4 + ((bs0 + j)*NN + dst)*32 + lane);
        acc[j] = make_float4(0.f, 0.f, 0.f, 0.f);
    }

    int s = __ldg(&g_off[dst]), e = __ldg(&g_off[dst+1]);
    if (s < e) {
        int2 pe = __ldg(&g_epk[s]);
        for (int k = s; k < e; k++) {
            int2 pen = (k + 1 < e) ? __ldg(&g_epk[k+1]) : pe;
            float4 r = __ldg(R4 + pe.y*32 + lane);
            float4 p[4];
            #pragma unroll
            for (int j = 0; j < 4; j++)
                p[j] = __ldg(P4 + ((bs0 + j)*NN + pe.x)*32 + lane);
            #pragma unroll
            for (int j = 0; j < 4; j++) {
                acc[j].x += gelu_f(p[j].x + q[j].x + r.x);
                acc[j].y += gelu_f(p[j].y + q[j].y + r.y);
                acc[j].z += gelu_f(p[j].z + q[j].z + r.z);
                acc[j].w += gelu_f(p[j].w + q[j].w + r.w);
            }
            pe = pen;
        }
    }
    #pragma unroll
    for (int j = 0; j < 4; j++)
        ((float4*)g_G)[((bs0 + j)*NN + dst)*32 + lane] = acc[j];
}

// ---------------- K5: update MLP via tf32 MMA + residual + LN ----------------
__global__ __launch_bounds__(512) void update_kernel(
    const float* __restrict__ mb2, const float* __restrict__ ub1,
    const float* __restrict__ ub2,
    const float* __restrict__ sg,  const float* __restrict__ sb)
{
    extern __shared__ float sm[];
    float* sG   = sm;               // 32 x 132 tf32
    float* sUin = sG + 4224;        // 32 x 132 tf32
    float* sHid = sUin + 4224;      // 32 x 68 tf32
    float* sXr  = sHid + 2176;      // 32 x 64 fp32
    float* sY   = sXr + 2048;       // 32 x 64
    float* smb2 = sY + 2048;        // 64
    float* sub1 = smb2 + 64;
    float* sub2 = sub1 + 64;
    float* ssg  = sub2 + 64;
    float* ssb  = ssg + 64;
    float* sdeg = ssb + 64;         // 32
    float* smean= sdeg + 32;        // 32
    float* sinv = smean + 32;       // 32

    int t = threadIdx.x;
    if (t < 64) { smb2[t] = mb2[t]; sub1[t] = ub1[t]; sub2[t] = ub2[t]; ssg[t] = sg[t]; ssb[t] = sb[t]; }

    int rbase = blockIdx.x * 32;
    for (int idx = t; idx < 4096; idx += 512) {
        int c = idx & 127, r = idx >> 7;
        sG[r*132 + c] = to_tf32(g_G[(rbase + r)*128 + c]);
    }
    for (int idx = t; idx < 2048; idx += 512) {
        int c = idx & 63, r = idx >> 6;
        float v = g_x1[(rbase + r)*64 + c];
        sXr[r*64 + c] = v;
        sUin[r*132 + c] = to_tf32(v);
    }
    if (t < 32) {
        int n = (rbase + t) % NN;
        sdeg[t] = (float)(g_off[n+1] - g_off[n]);
    }
    __syncthreads();

    int w = t >> 5, lane = t & 31, g = lane >> 2, tg = lane & 3;
    int mt = w >> 3, nt = w & 7;
    int col = nt*8 + 2*tg;
    int r0 = mt*16 + g;

    // Stage0: aggr = G @ mw2 + deg*mb2
    {
        float4 d = make_float4(sdeg[r0]*smb2[col],   sdeg[r0]*smb2[col+1],
                               sdeg[r0+8]*smb2[col], sdeg[r0+8]*smb2[col+1]);
        #pragma unroll
        for (int kt = 0; kt < 16; kt++) {
            const float* Ab = sG + (mt*16)*132 + kt*8;
            float a0 = Ab[g*132 + tg],     a1 = Ab[(g+8)*132 + tg];
            float a2 = Ab[g*132 + tg + 4], a3 = Ab[(g+8)*132 + tg + 4];
            float2 b = __ldg((const float2*)&g_W2f[((((kt<<3) + nt)<<5) + lane)*2]);
            mma_tf32(d, a0, a1, a2, a3, b.x, b.y);
        }
        *(float2*)&sUin[r0*132 + 64 + col]     = make_float2(to_tf32(d.x), to_tf32(d.y));
        *(float2*)&sUin[(r0+8)*132 + 64 + col] = make_float2(to_tf32(d.z), to_tf32(d.w));
    }
    __syncthreads();

    // Stage1: hid = gelu(Uin @ uw1 + ub1)
    {
        float4 d = make_float4(sub1[col], sub1[col+1], sub1[col], sub1[col+1]);
        #pragma unroll
        for (int kt = 0; kt < 16; kt++) {
            const float* Ab = sUin + (mt*16)*132 + kt*8;
            float a0 = Ab[g*132 + tg],     a1 = Ab[(g+8)*132 + tg];
            float a2 = Ab[g*132 + tg + 4], a3 = Ab[(g+8)*132 + tg + 4];
            float2 b = __ldg((const float2*)&g_U1f[((((kt<<3) + nt)<<5) + lane)*2]);
            mma_tf32(d, a0, a1, a2, a3, b.x, b.y);
        }
        *(float2*)&sHid[r0*68 + col]     = make_float2(to_tf32(gelu_f(d.x)), to_tf32(gelu_f(d.y)));
        *(float2*)&sHid[(r0+8)*68 + col] = make_float2(to_tf32(gelu_f(d.z)), to_tf32(gelu_f(d.w)));
    }
    __syncthreads();

    // Stage2: y = xs + hid @ uw2 + ub2
    {
        float4 d = make_float4(sub2[col], sub2[col+1], sub2[col], sub2[col+1]);
        #pragma unroll
        for (int kt = 0; kt < 8; kt++) {
            const float* Ab = sHid + (mt*16)*68 + kt*8;
            float a0 = Ab[g*68 + tg],     a1 = Ab[(g+8)*68 + tg];
            float a2 = Ab[g*68 + tg + 4], a3 = Ab[(g+8)*68 + tg + 4];
            float2 b = __ldg((const float2*)&g_U2f[((((kt<<3) + nt)<<5) + lane)*2]);
            mma_tf32(d, a0, a1, a2, a3, b.x, b.y);
        }
        sY[r0*64 + col]       = sXr[r0*64 + col]       + d.x;
        sY[r0*64 + col+1]     = sXr[r0*64 + col+1]     + d.y;
        sY[(r0+8)*64 + col]   = sXr[(r0+8)*64 + col]   + d.z;
        sY[(r0+8)*64 + col+1] = sXr[(r0+8)*64 + col+1] + d.w;
    }
    __syncthreads();

    // LN
    {
        int r = t >> 4, l = t & 15;
        float4 v = *(const float4*)&sY[r*64 + l*4];
        float s  = v.x + v.y + v.z + v.w;
        float ss = v.x*v.x + v.y*v.y + v.z*v.z + v.w*v.w;
        #pragma unroll
        for (int o = 1; o < 16; o <<= 1) {
            s  += __shfl_xor_sync(0xffffffffu, s,  o, 16);
            ss += __shfl_xor_sync(0xffffffffu, ss, o, 16);
        }
        if (l == 0) {
            float m = s * (1.f/64.f);
            float var = ss * (1.f/64.f) - m*m;
            smean[r] = m; sinv[r] = rsqrtf(var + 1e-5f);
        }
    }
    __syncthreads();
    for (int i = t; i < 2048; i += 512) {
        int r = i >> 6, cc = i & 63;
        g_x2[(rbase + r)*64 + cc] = (sY[i] - smean[r]) * sinv[r] * ssg[cc] + ssb[cc];
    }
}

// ---------------- K6: FFN via tf32 MMA + residual + LN -> d_out --------------
__global__ __launch_bounds__(512) void ffn_kernel(
    const float* __restrict__ fb1, const float* __restrict__ fb2,
    const float* __restrict__ fg,  const float* __restrict__ fb,
    float* __restrict__ out)
{
    extern __shared__ float sm[];
    float* sA   = sm;               // X 32 x 68 tf32
    float* sH   = sA + 2176;        // H 32 x 260 tf32
    float* sXr  = sH + 8320;        // 32 x 64 fp32
    float* sY   = sXr + 2048;       // 32 x 64
    float* sb1  = sY + 2048;        // 256
    float* sb2  = sb1 + 256;        // 64
    float* sfg  = sb2 + 64;
    float* sfb  = sfg + 64;
    float* smean= sfb + 64;         // 32
    float* sinv = smean + 32;       // 32

    int t = threadIdx.x;
    if (t < 256) sb1[t] = fb1[t];
    if (t < 64) { sb2[t] = fb2[t]; sfg[t] = fg[t]; sfb[t] = fb[t]; }

    int rbase = blockIdx.x * 32;
    for (int idx = t; idx < 2048; idx += 512) {
        int c = idx & 63, r = idx >> 6;
        float v = g_x2[(rbase + r)*64 + c];
        sXr[r*64 + c] = v;
        sA[r*68 + c] = to_tf32(v);
    }
    __syncthreads();

    int w = t >> 5, lane = t & 31, g = lane >> 2, tg = lane & 3;

    // Stage1: H = gelu(X @ W1 + b1)
    {
        int mt = w >> 3, ng = w & 7;
        float4 d[4];
        #pragma unroll
        for (int i = 0; i < 4; i++) {
            int col = (ng*4 + i)*8 + 2*tg;
            d[i] = make_float4(sb1[col], sb1[col+1], sb1[col], sb1[col+1]);
        }
        #pragma unroll
        for (int kt = 0; kt < 8; kt++) {
            const float* Ab = sA + (mt*16)*68 + kt*8;
            float a0 = Ab[g*68 + tg],     a1 = Ab[(g+8)*68 + tg];
            float a2 = Ab[g*68 + tg + 4], a3 = Ab[(g+8)*68 + tg + 4];
            #pragma unroll
            for (int i = 0; i < 4; i++) {
                int nt = ng*4 + i;
                float2 b = __ldg((const float2*)&g_F1f[((((kt<<5) + nt)<<5) + lane)*2]);
                mma_tf32(d[i], a0, a1, a2, a3, b.x, b.y);
            }
        }
        int r0 = mt*16 + g;
        #pragma unroll
        for (int i = 0; i < 4; i++) {
            int col = (ng*4 + i)*8 + 2*tg;
            *(float2*)&sH[r0*260 + col]     = make_float2(to_tf32(gelu_f(d[i].x)), to_tf32(gelu_f(d[i].y)));
            *(float2*)&sH[(r0+8)*260 + col] = make_float2(to_tf32(gelu_f(d[i].z)), to_tf32(gelu_f(d[i].w)));
        }
    }
    __syncthreads();

    // Stage2: Y = X + H @ W2 + b2
    {
        int mt = w >> 3, nt = w & 7;
        int col = nt*8 + 2*tg;
        int r0 = mt*16 + g;
        float4 d = make_float4(sb2[col], sb2[col+1], sb2[col], sb2[col+1]);
        #pragma unroll
        for (int kt = 0; kt < 32; kt++) {
            const float* Ab = sH + (mt*16)*260 + kt*8;
            float a0 = Ab[g*260 + tg],     a1 = Ab[(g+8)*260 + tg];
            float a2 = Ab[g*260 + tg + 4], a3 = Ab[(g+8)*260 + tg + 4];
            float2 b = __ldg((const float2*)&g_F2f[((((kt<<3) + nt)<<5) + lane)*2]);
            mma_tf32(d, a0, a1, a2, a3, b.x, b.y);
        }
        sY[r0*64 + col]       = sXr[r0*64 + col]       + d.x;
        sY[r0*64 + col+1]     = sXr[r0*64 + col+1]     + d.y;
        sY[(r0+8)*64 + col]   = sXr[(r0+8)*64 + col]   + d.z;
        sY[(r0+8)*64 + col+1] = sXr[(r0+8)*64 + col+1] + d.w;
    }
    __syncthreads();

    // LN
    {
        int r = t >> 4, l = t & 15;
        float4 v = *(const float4*)&sY[r*64 + l*4];
        float s  = v.x + v.y + v.z + v.w;
        float ss = v.x*v.x + v.y*v.y + v.z*v.z + v.w*v.w;
        #pragma unroll
        for (int o = 1; o < 16; o <<= 1) {
            s  += __shfl_xor_sync(0xffffffffu, s,  o, 16);
            ss += __shfl_xor_sync(0xffffffffu, ss, o, 16);
        }
        if (l == 0) {
            float m = s * (1.f/64.f);
            float var = ss * (1.f/64.f) - m*m;
            smean[r] = m; sinv[r] = rsqrtf(var + 1e-5f);
        }
    }
    __syncthreads();
    for (int i = t; i < 2048; i += 512) {
        int r = i >> 6, cc = i & 63;
        out[(rbase + r)*64 + cc] = (sY[i] - smean[r]) * sinv[r] * sfg[cc] + sfb[cc];
    }
}

// ---------------- host launcher ---------------------------------------------
extern "C" void kernel_launch(void* const* d_in, const int* in_sizes, int n_in,
                              void* d_out, int out_size)
{
    (void)in_sizes; (void)n_in; (void)out_size;
    const float* x    = (const float*)d_in[0];
    const int*   ei   = (const int*)  d_in[1];
    const float* ea   = (const float*)d_in[2];
    const float* ipw  = (const float*)d_in[3];
    const float* ipb  = (const float*)d_in[4];
    const float* opw  = (const float*)d_in[5];
    const float* opb  = (const float*)d_in[6];
    const float* tng  = (const float*)d_in[7];
    const float* tnb  = (const float*)d_in[8];
    const float* ew1  = (const float*)d_in[9];
    const float* eb1  = (const float*)d_in[10];
    const float* ew2  = (const float*)d_in[11];
    const float* eb2  = (const float*)d_in[12];
    const float* mw1  = (const float*)d_in[13];
    const float* mb1  = (const float*)d_in[14];
    const float* mw2  = (const float*)d_in[15];
    const float* mb2  = (const float*)d_in[16];
    const float* uw1  = (const float*)d_in[17];
    const float* ub1  = (const float*)d_in[18];
    const float* uw2  = (const float*)d_in[19];
    const float* ub2  = (const float*)d_in[20];
    const float* sng  = (const float*)d_in[21];
    const float* snb  = (const float*)d_in[22];
    const float* fw1  = (const float*)d_in[23];
    const float* fb1  = (const float*)d_in[24];
    const float* fw2  = (const float*)d_in[25];
    const float* fb2  = (const float*)d_in[26];
    const float* fng  = (const float*)d_in[27];
    const float* fnb  = (const float*)d_in[28];
    float* out = (float*)d_out;

    const int SM_ATT = 25344 * 4;   // 101376
    const int SM_EE  = 4672 * 4;    // 18688
    const int SM_PQ  = 2176 * 4;    // 8704
    const int SM_UPD = 15136 * 4;   // 60544
    const int SM_FFN = 15104 * 4;   // 60416
    cudaFuncSetAttribute(attn_kernel,     cudaFuncAttributeMaxDynamicSharedMemorySize, SM_ATT);
    cudaFuncSetAttribute(edge_emb_kernel, cudaFuncAttributeMaxDynamicSharedMemorySize, SM_EE);
    cudaFuncSetAttribute(pq_kernel,       cudaFuncAttributeMaxDynamicSharedMemorySize, SM_PQ);
    cudaFuncSetAttribute(update_kernel,   cudaFuncAttributeMaxDynamicSharedMemorySize, SM_UPD);
    cudaFuncSetAttribute(ffn_kernel,      cudaFuncAttributeMaxDynamicSharedMemorySize, SM_FFN);

    // position 4 gets captured by ncu -> new edge_emb this time
    prep_kernel      <<<202, 512>>>(ipw, opw, mw1, mw2, uw1, uw2, fw1, fw2, ew2);
    attn_kernel      <<<2500, 512, SM_ATT>>>(x, ipb, opb, tng, tnb);
    csr_count_kernel <<<79, 256>>>(ei);
    edge_emb_kernel  <<<625, 512, SM_EE>>>(ea, ew1, eb1, eb2, mb1);
    pq_kernel        <<<5000, 512, SM_PQ>>>();
    csr_scan_kernel  <<<1, 1024>>>();
    csr_fill_kernel  <<<79, 256>>>(ei);
    aggr_kernel      <<<5000, 256>>>();
    update_kernel    <<<5000, 512, SM_UPD>>>(mb2, ub1, ub2, sng, snb);
    ffn_kernel       <<<5000, 512, SM_FFN>>>(fb1, fb2, fng, fnb, out);
}

// round 14
// speedup vs baseline: 1.1908x; 1.0562x over previous
#include <cuda_runtime.h>

// ---------------- problem constants ----------------
#define BB    2
#define SS    16
#define NN    5000
#define HH    64
#define EE    20000
#define BSS   (BB*SS)      // 32
#define BNN   (BB*NN)      // 10000
#define NROWS (BSS*NN)     // 160000

// ---------------- scratch (device globals) ----------------
__device__ __align__(16) float g_x1[NROWS*HH];
__device__ __align__(16) float g_x2[NROWS*HH];
__device__ __align__(16) float g_P [NROWS*128];
__device__ __align__(16) float g_Q [NROWS*128];
__device__ __align__(16) float g_R [EE*128];
__device__ int  g_cnt[NN];
__device__ int  g_cur[NN];
__device__ int  g_off[NN+1];
__device__ int2 g_epk[EE];     // (src, e) sorted by dst

// fragment-permuted weights (filled once per launch by prep_kernel)
__device__ __align__(16) float g_Wif [12288];   // in_proj 64x192, NT=24
__device__ __align__(16) float g_Wof [4096];    // out_proj 64x64, NT=8
__device__ __align__(16) float g_Wpqf[16384];   // [Wa-Wb | Wb] 64x256, NT=32
__device__ __align__(16) float g_W2f [8192];    // mw2 128x64, NT=8
__device__ __align__(16) float g_U1f [8192];    // uw1 128x64, NT=8
__device__ __align__(16) float g_U2f [4096];    // uw2 64x64, NT=8
__device__ __align__(16) float g_F1f [16384];   // fw1 64x256, NT=32
__device__ __align__(16) float g_F2f [16384];   // fw2 256x64, NT=8
__device__ __align__(16) float g_E2f [4096];    // ew2 64x64, NT=8
__device__ __align__(16) float g_Wcf [8192];    // mw1 rows 128..191 (64x128), NT=16

__device__ __forceinline__ float gelu_f(float v) {
    return 0.5f * v * (1.0f + erff(v * 0.70710678118654752f));
}

__device__ __forceinline__ float to_tf32(float x) {
    unsigned r;
    asm("cvt.rna.tf32.f32 %0, %1;" : "=r"(r) : "f"(x));
    return __uint_as_float(r);
}

__device__ __forceinline__ int fragidx(int k, int c, int NT) {
    int kt = k >> 3, kk = k & 7, j = kk >> 2, tg = kk & 3;
    int nt = c >> 3, gg = c & 7;
    return ((kt*NT + nt)*32 + (gg<<2) + tg)*2 + j;
}

// mma.m16n8k8 tf32: D(16x8) += A(16x8,row) * B(8x8,col)
__device__ __forceinline__ void mma_tf32(float4& d,
    float a0, float a1, float a2, float a3, float b0, float b1)
{
    asm volatile(
      "mma.sync.aligned.m16n8k8.row.col.f32.tf32.tf32.f32 "
      "{%0,%1,%2,%3},{%4,%5,%6,%7},{%8,%9},{%0,%1,%2,%3};\n"
      : "+f"(d.x), "+f"(d.y), "+f"(d.z), "+f"(d.w)
      : "r"(__float_as_uint(a0)), "r"(__float_as_uint(a1)),
        "r"(__float_as_uint(a2)), "r"(__float_as_uint(a3)),
        "r"(__float_as_uint(b0)), "r"(__float_as_uint(b1)));
}

// ---------------- prep: permute weights + zero CSR counters -----------------
__global__ void prep_kernel(
    const float* __restrict__ Wi,  const float* __restrict__ Wo,
    const float* __restrict__ mw1, const float* __restrict__ mw2,
    const float* __restrict__ uw1, const float* __restrict__ uw2,
    const float* __restrict__ fw1, const float* __restrict__ fw2,
    const float* __restrict__ ew2)
{
    int i = blockIdx.x * 512 + threadIdx.x;   // grid 202*512
    if (i < 12288) {                              // Wi 64x192
        int k = i / 192, c = i % 192;
        g_Wif[fragidx(k, c, 24)] = to_tf32(Wi[i]);
    } else if (i < 16384) {                       // Wo 64x64
        int idx = i - 12288, k = idx >> 6, c = idx & 63;
        g_Wof[fragidx(k, c, 8)] = to_tf32(Wo[idx]);
    } else if (i < 32768) {                       // pq combined 64x256
        int idx = i - 16384, k = idx >> 8, c = idx & 255;
        float w = (c < 128) ? (mw1[k*128 + c] - mw1[(64+k)*128 + c])
                            :  mw1[(64+k)*128 + (c-128)];
        g_Wpqf[fragidx(k, c, 32)] = to_tf32(w);
    } else if (i < 40960) {                       // mw2 128x64
        int idx = i - 32768, k = idx >> 6, c = idx & 63;
        g_W2f[fragidx(k, c, 8)] = to_tf32(mw2[idx]);
    } else if (i < 49152) {                       // uw1 128x64
        int idx = i - 40960, k = idx >> 6, c = idx & 63;
        g_U1f[fragidx(k, c, 8)] = to_tf32(uw1[idx]);
    } else if (i < 53248) {                       // uw2 64x64
        int idx = i - 49152, k = idx >> 6, c = idx & 63;
        g_U2f[fragidx(k, c, 8)] = to_tf32(uw2[idx]);
    } else if (i < 69632) {                       // fw1 64x256
        int idx = i - 53248, k = idx >> 8, c = idx & 255;
        g_F1f[fragidx(k, c, 32)] = to_tf32(fw1[idx]);
    } else if (i < 86016) {                       // fw2 256x64
        int idx = i - 69632, k = idx >> 6, c = idx & 63;
        g_F2f[fragidx(k, c, 8)] = to_tf32(fw2[idx]);
    } else if (i < 90112) {                       // ew2 64x64
        int idx = i - 86016, k = idx >> 6, c = idx & 63;
        g_E2f[fragidx(k, c, 8)] = to_tf32(ew2[idx]);
    } else if (i < 98304) {                       // Wc = mw1 rows 128..191, 64x128
        int idx = i - 90112, k = idx >> 7, c = idx & 127;
        g_Wcf[fragidx(k, c, 16)] = to_tf32(mw1[(128 + k)*128 + c]);
    } else if (i < 98304 + NN) {                  // zero CSR counters
        g_cnt[i - 98304] = 0;
    }
}

// ---------------- CSR build ----------------
__global__ void csr_count_kernel(const int* __restrict__ ei) {
    int e = blockIdx.x * blockDim.x + threadIdx.x;
    if (e < EE) atomicAdd(&g_cnt[ei[EE + e]], 1);
}
__global__ void csr_scan_kernel() {
    __shared__ int sbuf[1024];
    __shared__ int scarry;
    int t = threadIdx.x;
    if (t == 0) scarry = 0;
    __syncthreads();
    for (int ch = 0; ch < 5; ch++) {
        int idx = ch * 1024 + t;
        int v = (idx < NN) ? g_cnt[idx] : 0;
        sbuf[t] = v; __syncthreads();
        for (int o = 1; o < 1024; o <<= 1) {
            int x = (t >= o) ? sbuf[t - o] : 0;
            __syncthreads();
            sbuf[t] += x;
            __syncthreads();
        }
        int incl = sbuf[t];
        int base = scarry;
        if (idx < NN) { int off = base + incl - v; g_off[idx] = off; g_cur[idx] = off; }
        __syncthreads();
        if (t == 1023) scarry = base + sbuf[1023];
        __syncthreads();
    }
    if (t == 0) g_off[NN] = scarry;
}
__global__ void csr_fill_kernel(const int* __restrict__ ei) {
    int e = blockIdx.x * blockDim.x + threadIdx.x;
    if (e < EE) {
        int dst = ei[EE + e];
        int pos = atomicAdd(&g_cur[dst], 1);
        g_epk[pos] = make_int2(ei[e], e);
    }
}

// ---------------- K1: temporal attention via tf32 MMA + residual + LN -------
__global__ __launch_bounds__(512, 2) void attn_kernel(
    const float* __restrict__ x,
    const float* __restrict__ bi, const float* __restrict__ bo,
    const float* __restrict__ tg_, const float* __restrict__ tb_)
{
    extern __shared__ float sm[];
    float* sbi  = sm;            // 192
    float* sbo  = sbi + 192;     // 64
    float* stg  = sbo + 64;      // 64
    float* stb  = stg + 64;      // 64
    float* sX   = stb + 64;      // 64x68 tf32 (also residual source)
    float* sqkvT= sX + 4352;     // [seq<4][j<192][s<16] pad20 = 15360
    float* saoT = sqkvT + 15360; // [seq<4][d<64][q<16] pad20 = 5120
    float* sY   = sqkvT;         // alias: sqkvT dead after softmax
    float* smean= saoT + 5120;   // 64
    float* sinv = smean + 64;    // 64

    int t = threadIdx.x;
    if (t < 192) sbi[t] = bi[t];
    if (t < 64) { sbo[t] = bo[t]; stg[t] = tg_[t]; stb[t] = tb_[t]; }

    int bn0 = blockIdx.x * 4;
    for (int idx = t; idx < 4096; idx += 512) {
        int row = idx >> 6, c = idx & 63;
        int seq = row >> 4, s = row & 15;
        int bn = bn0 + seq;
        int b = bn / NN, n = bn % NN;
        sX[row*68 + c] = to_tf32(x[((b*SS + s)*NN + n)*HH + c]);
    }
    __syncthreads();

    int w = t >> 5, lane = t & 31, g = lane >> 2, tg = lane & 3;

    // qkv = X @ Wi + bi : M=64, N=192, K=64. warp: mt=w>>2, 6 n-tiles
    {
        int mt = w >> 2, ng = w & 3;
        float4 d[6];
        #pragma unroll
        for (int i = 0; i < 6; i++) {
            int col = (ng*6 + i)*8 + 2*tg;
            d[i] = make_float4(sbi[col], sbi[col+1], sbi[col], sbi[col+1]);
        }
        #pragma unroll
        for (int kt = 0; kt < 8; kt++) {
            const float* Ab = sX + (mt*16)*68 + kt*8;
            float a0 = Ab[g*68 + tg],     a1 = Ab[(g+8)*68 + tg];
            float a2 = Ab[g*68 + tg + 4], a3 = Ab[(g+8)*68 + tg + 4];
            #pragma unroll
            for (int i = 0; i < 6; i++) {
                int nt = ng*6 + i;
                float2 b = __ldg((const float2*)&g_Wif[((kt*24 + nt)*32 + lane)*2]);
                mma_tf32(d[i], a0, a1, a2, a3, b.x, b.y);
            }
        }
        #pragma unroll
        for (int i = 0; i < 6; i++) {
            int col = (ng*6 + i)*8 + 2*tg;
            float* base = sqkvT + (mt*192 + col)*20;
            base[g]        = d[i].x;
            base[20 + g]   = d[i].y;
            base[g + 8]    = d[i].z;
            base[20 + g+8] = d[i].w;
        }
    }
    __syncthreads();

    // attention core (exact fp32): thread = (seq, head, q), 256 active
    if (t < 256) {
        int seq = t >> 6, h = (t >> 4) & 3, q = t & 15;
        const float* Qb = sqkvT + (seq*192 + h*16)*20;
        const float* Kb = Qb + 64*20;
        const float* Vb = Qb + 128*20;
        float sc[16];
        #pragma unroll
        for (int k = 0; k < 16; k++) sc[k] = 0.f;
        #pragma unroll
        for (int d = 0; d < 16; d++) {
            float qv = Qb[d*20 + q];
            const float4* kk = (const float4*)(Kb + d*20);
            float4 k0 = kk[0], k1 = kk[1], k2 = kk[2], k3 = kk[3];
            sc[0]+=qv*k0.x; sc[1]+=qv*k0.y; sc[2]+=qv*k0.z; sc[3]+=qv*k0.w;
            sc[4]+=qv*k1.x; sc[5]+=qv*k1.y; sc[6]+=qv*k1.z; sc[7]+=qv*k1.w;
            sc[8]+=qv*k2.x; sc[9]+=qv*k2.y; sc[10]+=qv*k2.z; sc[11]+=qv*k2.w;
            sc[12]+=qv*k3.x; sc[13]+=qv*k3.y; sc[14]+=qv*k3.z; sc[15]+=qv*k3.w;
        }
        float mx = -1e30f;
        #pragma unroll
        for (int k = 0; k < 16; k++) { sc[k] *= 0.25f; mx = fmaxf(mx, sc[k]); }
        float den = 0.f;
        #pragma unroll
        for (int k = 0; k < 16; k++) { sc[k] = expf(sc[k] - mx); den += sc[k]; }
        float inv = 1.f / den;
        #pragma unroll
        for (int d = 0; d < 16; d++) {
            const float4* vv = (const float4*)(Vb + d*20);
            float4 v0 = vv[0], v1 = vv[1], v2 = vv[2], v3 = vv[3];
            float o = sc[0]*v0.x + sc[1]*v0.y + sc[2]*v0.z + sc[3]*v0.w
                    + sc[4]*v1.x + sc[5]*v1.y + sc[6]*v1.z + sc[7]*v1.w
                    + sc[8]*v2.x + sc[9]*v2.y + sc[10]*v2.z + sc[11]*v2.w
                    + sc[12]*v3.x + sc[13]*v3.y + sc[14]*v3.z + sc[15]*v3.w;
            saoT[(seq*64 + h*16 + d)*20 + q] = to_tf32(o * inv);
        }
    }
    __syncthreads();

    // out-proj: Y = X + AO @ Wo + bo
    {
        int mt = w >> 2, np = w & 3;
        float4 d[2];
        #pragma unroll
        for (int i = 0; i < 2; i++) {
            int col = (np*2 + i)*8 + 2*tg;
            d[i] = make_float4(sbo[col], sbo[col+1], sbo[col], sbo[col+1]);
        }
        #pragma unroll
        for (int kt = 0; kt < 8; kt++) {
            const float* Ab = saoT + (mt*64 + kt*8)*20;
            float a0 = Ab[tg*20 + g],       a1 = Ab[tg*20 + g + 8];
            float a2 = Ab[(tg+4)*20 + g],   a3 = Ab[(tg+4)*20 + g + 8];
            #pragma unroll
            for (int i = 0; i < 2; i++) {
                int nt = np*2 + i;
                float2 b = __ldg((const float2*)&g_Wof[((((kt<<3) + nt)<<5) + lane)*2]);
                mma_tf32(d[i], a0, a1, a2, a3, b.x, b.y);
            }
        }
        int r0 = mt*16 + g;
        #pragma unroll
        for (int i = 0; i < 2; i++) {
            int col = (np*2 + i)*8 + 2*tg;
            sY[r0*64 + col]       = sX[r0*68 + col]       + d[i].x;
            sY[r0*64 + col+1]     = sX[r0*68 + col+1]     + d[i].y;
            sY[(r0+8)*64 + col]   = sX[(r0+8)*68 + col]   + d[i].z;
            sY[(r0+8)*64 + col+1] = sX[(r0+8)*68 + col+1] + d[i].w;
        }
    }
    __syncthreads();

    // LN: 64 rows, 8 lanes per row
    {
        int r = t >> 3, l = t & 7;
        float4 v1 = *(const float4*)&sY[r*64 + l*8];
        float4 v2 = *(const float4*)&sY[r*64 + l*8 + 4];
        float s  = v1.x+v1.y+v1.z+v1.w + v2.x+v2.y+v2.z+v2.w;
        float ss = v1.x*v1.x+v1.y*v1.y+v1.z*v1.z+v1.w*v1.w
                 + v2.x*v2.x+v2.y*v2.y+v2.z*v2.z+v2.w*v2.w;
        #pragma unroll
        for (int o = 1; o < 8; o <<= 1) {
            s  += __shfl_xor_sync(0xffffffffu, s,  o, 8);
            ss += __shfl_xor_sync(0xffffffffu, ss, o, 8);
        }
        if (l == 0) {
            float m = s * (1.f/64.f);
            float var = ss * (1.f/64.f) - m*m;
            smean[r] = m; sinv[r] = rsqrtf(var + 1e-5f);
        }
    }
    __syncthreads();
    for (int idx = t; idx < 4096; idx += 512) {
        int row = idx >> 6, c = idx & 63;
        int seq = row >> 4, s = row & 15;
        int bn = bn0 + seq;
        int b = bn / NN, n = bn % NN;
        g_x1[((b*SS + s)*NN + n)*HH + c] =
            (sY[idx] - smean[row]) * sinv[row] * stg[c] + stb[c];
    }
}

// ---------------- K2: edge embedding -> R via tf32 MMA ----------------------
__global__ __launch_bounds__(512) void edge_emb_kernel(
    const float* __restrict__ ea,
    const float* __restrict__ ew1, const float* __restrict__ eb1,
    const float* __restrict__ eb2, const float* __restrict__ mb1)
{
    extern __shared__ float sm[];
    float* sE0  = sm;          // 32x68 tf32
    float* sE2  = sm + 2176;   // 32x68 tf32
    float* sew1 = sm + 4352;   // 64
    float* seb1 = sew1 + 64;   // 64
    float* seb2 = seb1 + 64;   // 64
    float* smb1 = seb2 + 64;   // 128

    int t = threadIdx.x;
    if (t < 64) { sew1[t] = ew1[t]; seb1[t] = eb1[t]; seb2[t] = eb2[t]; }
    else if (t < 192) smb1[t-64] = mb1[t-64];
    int e0 = blockIdx.x * 32;
    __syncthreads();

    // Stage0: E0 = gelu(ea * ew1 + eb1) per edge-row
    for (int idx = t; idx < 2048; idx += 512) {
        int r = idx >> 6, c = idx & 63;
        sE0[r*68 + c] = to_tf32(gelu_f(__ldg(&ea[e0 + r]) * sew1[c] + seb1[c]));
    }
    __syncthreads();

    int w = t >> 5, lane = t & 31, g = lane >> 2, tg = lane & 3;

    // Stage1: E2 = E0 @ ew2 + eb2 : M=32, N=64, K=64
    {
        int mt = w >> 3, nt = w & 7;
        int col = nt*8 + 2*tg;
        int r0 = mt*16 + g;
        float4 d = make_float4(seb2[col], seb2[col+1], seb2[col], seb2[col+1]);
        #pragma unroll
        for (int kt = 0; kt < 8; kt++) {
            const float* Ab = sE0 + (mt*16)*68 + kt*8;
            float a0 = Ab[g*68 + tg],     a1 = Ab[(g+8)*68 + tg];
            float a2 = Ab[g*68 + tg + 4], a3 = Ab[(g+8)*68 + tg + 4];
            float2 b = __ldg((const float2*)&g_E2f[((((kt<<3) + nt)<<5) + lane)*2]);
            mma_tf32(d, a0, a1, a2, a3, b.x, b.y);
        }
        *(float2*)&sE2[r0*68 + col]     = make_float2(to_tf32(d.x), to_tf32(d.y));
        *(float2*)&sE2[(r0+8)*68 + col] = make_float2(to_tf32(d.z), to_tf32(d.w));
    }
    __syncthreads();

    // Stage2: R = E2 @ Wc + mb1 : M=32, N=128, K=64 (warp does 2 n-tiles)
    {
        int mt = w >> 3, ng = w & 7;
        float4 d[2];
        #pragma unroll
        for (int i = 0; i < 2; i++) {
            int col = (ng*2 + i)*8 + 2*tg;
            d[i] = make_float4(smb1[col], smb1[col+1], smb1[col], smb1[col+1]);
        }
        #pragma unroll
        for (int kt = 0; kt < 8; kt++) {
            const float* Ab = sE2 + (mt*16)*68 + kt*8;
            float a0 = Ab[g*68 + tg],     a1 = Ab[(g+8)*68 + tg];
            float a2 = Ab[g*68 + tg + 4], a3 = Ab[(g+8)*68 + tg + 4];
            #pragma unroll
            for (int i = 0; i < 2; i++) {
                int nt = ng*2 + i;
                float2 b = __ldg((const float2*)&g_Wcf[((kt*16 + nt)*32 + lane)*2]);
                mma_tf32(d[i], a0, a1, a2, a3, b.x, b.y);
            }
        }
        int r0 = mt*16 + g;
        #pragma unroll
        for (int i = 0; i < 2; i++) {
            int col = (ng*2 + i)*8 + 2*tg;
            *(float2*)&g_R[(e0 + r0)*128 + col]     = make_float2(d[i].x, d[i].y);
            *(float2*)&g_R[(e0 + r0 + 8)*128 + col] = make_float2(d[i].z, d[i].w);
        }
    }
}

// ---------------- K3: P,Q node GEMM via tf32 MMA (smem-staged stores) -------
__global__ __launch_bounds__(512) void pq_kernel()
{
    extern __shared__ float sm[];
    float* sA   = sm;          // 32 x 68 (tf32)
    float* sOut = sm + 2176;   // 32 x 260 (fp32 results, padded)

    int t = threadIdx.x;
    int rbase = blockIdx.x * 32;
    for (int idx = t; idx < 2048; idx += 512) {
        int r = idx >> 6, c = idx & 63;
        sA[r*68 + c] = to_tf32(g_x1[(rbase + r)*64 + c]);
    }
    __syncthreads();

    int w = t >> 5, lane = t & 31, g = lane >> 2, tg = lane & 3;
    int mt = w >> 3, ng = w & 7;
    float4 d[4];
    #pragma unroll
    for (int i = 0; i < 4; i++) d[i] = make_float4(0.f, 0.f, 0.f, 0.f);

    #pragma unroll
    for (int kt = 0; kt < 8; kt++) {
        const float* Ab = sA + (mt*16)*68 + kt*8;
        float a0 = Ab[g*68 + tg],     a1 = Ab[(g+8)*68 + tg];
        float a2 = Ab[g*68 + tg + 4], a3 = Ab[(g+8)*68 + tg + 4];
        #pragma unroll
        for (int i = 0; i < 4; i++) {
            int nt = ng*4 + i;
            float2 b = __ldg((const float2*)&g_Wpqf[((((kt<<5) + nt)<<5) + lane)*2]);
            mma_tf32(d[i], a0, a1, a2, a3, b.x, b.y);
        }
    }

    // stage results in smem
    {
        int r0 = mt*16 + g;
        #pragma unroll
        for (int i = 0; i < 4; i++) {
            int col = (ng*4 + i)*8 + 2*tg;
            *(float2*)&sOut[r0*260 + col]     = make_float2(d[i].x, d[i].y);
            *(float2*)&sOut[(r0+8)*260 + col] = make_float2(d[i].z, d[i].w);
        }
    }
    __syncthreads();

    // coalesced writeout: warp covers 32 consecutive floats of a row
    for (int idx = t; idx < 8192; idx += 512) {
        int r = idx >> 8, c = idx & 255;
        float v = sOut[r*260 + c];
        if (c < 128) g_P[(rbase + r)*128 + c] = v;
        else         g_Q[(rbase + r)*128 + (c - 128)] = v;
    }
}

// ---------------- K5: fused gather + update MLP + residual + LN -------------
// Block = 32 consecutive (bs,n) rows. Warp w gathers rows w*2..w*2+1 from CSR
// (16 warps x 2 = 32 rows), writing tf32 G-tile into smem; then MMA pipeline.
__global__ __launch_bounds__(512) void update_kernel(
    const float* __restrict__ mb2, const float* __restrict__ ub1,
    const float* __restrict__ ub2,
    const float* __restrict__ sg,  const float* __restrict__ sb)
{
    extern __shared__ float sm[];
    float* sG   = sm;               // 32 x 132 tf32
    float* sUin = sG + 4224;        // 32 x 132 tf32
    float* sHid = sUin + 4224;      // 32 x 68 tf32
    float* sXr  = sHid + 2176;      // 32 x 64 fp32
    float* sY   = sXr + 2048;       // 32 x 64
    float* smb2 = sY + 2048;        // 64
    float* sub1 = smb2 + 64;
    float* sub2 = sub1 + 64;
    float* ssg  = sub2 + 64;
    float* ssb  = ssg + 64;
    float* sdeg = ssb + 64;         // 32
    float* smean= sdeg + 32;        // 32
    float* sinv = smean + 32;       // 32

    int t = threadIdx.x;
    if (t < 64) { smb2[t] = mb2[t]; sub1[t] = ub1[t]; sub2[t] = ub2[t]; ssg[t] = sg[t]; ssb[t] = sb[t]; }

    int rbase = blockIdx.x * 32;
    for (int idx = t; idx < 2048; idx += 512) {
        int c = idx & 63, r = idx >> 6;
        float v = g_x1[(rbase + r)*64 + c];
        sXr[r*64 + c] = v;
        sUin[r*132 + c] = to_tf32(v);
    }

    int w = t >> 5, lane = t & 31;

    // fused CSR gather: warp w accumulates rows w*2, w*2+1 into sG (tf32)
    {
        const float4* P4 = (const float4*)g_P;
        const float4* Q4 = (const float4*)g_Q;
        const float4* R4 = (const float4*)g_R;
        #pragma unroll
        for (int j = 0; j < 2; j++) {
            int lr = w*2 + j;                 // local row 0..31
            int row = rbase + lr;
            int bs = row / NN, n = row - bs*NN;
            float4 q = __ldg(Q4 + row*32 + lane);
            float4 acc = make_float4(0.f, 0.f, 0.f, 0.f);
            int s = __ldg(&g_off[n]), e = __ldg(&g_off[n+1]);
            if (s < e) {
                int2 pe = __ldg(&g_epk[s]);
                for (int k = s; k < e; k++) {
                    int2 pen = (k + 1 < e) ? __ldg(&g_epk[k+1]) : pe;
                    float4 p = __ldg(P4 + (bs*NN + pe.x)*32 + lane);
                    float4 r = __ldg(R4 + pe.y*32 + lane);
                    acc.x += gelu_f(p.x + q.x + r.x);
                    acc.y += gelu_f(p.y + q.y + r.y);
                    acc.z += gelu_f(p.z + q.z + r.z);
                    acc.w += gelu_f(p.w + q.w + r.w);
                    pe = pen;
                }
            }
            *(float4*)&sG[lr*132 + lane*4] =
                make_float4(to_tf32(acc.x), to_tf32(acc.y),
                            to_tf32(acc.z), to_tf32(acc.w));
            if (lane == 0) sdeg[lr] = (float)(e - s);
        }
    }
    __syncthreads();

    int g = lane >> 2, tg = lane & 3;
    int mt = w >> 3, nt = w & 7;
    int col = nt*8 + 2*tg;
    int r0 = mt*16 + g;

    // Stage0: aggr = G @ mw2 + deg*mb2
    {
        float4 d = make_float4(sdeg[r0]*smb2[col],   sdeg[r0]*smb2[col+1],
                               sdeg[r0+8]*smb2[col], sdeg[r0+8]*smb2[col+1]);
        #pragma unroll
        for (int kt = 0; kt < 16; kt++) {
            const float* Ab = sG + (mt*16)*132 + kt*8;
            float a0 = Ab[g*132 + tg],     a1 = Ab[(g+8)*132 + tg];
            float a2 = Ab[g*132 + tg + 4], a3 = Ab[(g+8)*132 + tg + 4];
            float2 b = __ldg((const float2*)&g_W2f[((((kt<<3) + nt)<<5) + lane)*2]);
            mma_tf32(d, a0, a1, a2, a3, b.x, b.y);
        }
        *(float2*)&sUin[r0*132 + 64 + col]     = make_float2(to_tf32(d.x), to_tf32(d.y));
        *(float2*)&sUin[(r0+8)*132 + 64 + col] = make_float2(to_tf32(d.z), to_tf32(d.w));
    }
    __syncthreads();

    // Stage1: hid = gelu(Uin @ uw1 + ub1)
    {
        float4 d = make_float4(sub1[col], sub1[col+1], sub1[col], sub1[col+1]);
        #pragma unroll
        for (int kt = 0; kt < 16; kt++) {
            const float* Ab = sUin + (mt*16)*132 + kt*8;
            float a0 = Ab[g*132 + tg],     a1 = Ab[(g+8)*132 + tg];
            float a2 = Ab[g*132 + tg + 4], a3 = Ab[(g+8)*132 + tg + 4];
            float2 b = __ldg((const float2*)&g_U1f[((((kt<<3) + nt)<<5) + lane)*2]);
            mma_tf32(d, a0, a1, a2, a3, b.x, b.y);
        }
        *(float2*)&sHid[r0*68 + col]     = make_float2(to_tf32(gelu_f(d.x)), to_tf32(gelu_f(d.y)));
        *(float2*)&sHid[(r0+8)*68 + col] = make_float2(to_tf32(gelu_f(d.z)), to_tf32(gelu_f(d.w)));
    }
    __syncthreads();

    // Stage2: y = xs + hid @ uw2 + ub2
    {
        float4 d = make_float4(sub2[col], sub2[col+1], sub2[col], sub2[col+1]);
        #pragma unroll
        for (int kt = 0; kt < 8; kt++) {
            const float* Ab = sHid + (mt*16)*68 + kt*8;
            float a0 = Ab[g*68 + tg],     a1 = Ab[(g+8)*68 + tg];
            float a2 = Ab[g*68 + tg + 4], a3 = Ab[(g+8)*68 + tg + 4];
            float2 b = __ldg((const float2*)&g_U2f[((((kt<<3) + nt)<<5) + lane)*2]);
            mma_tf32(d, a0, a1, a2, a3, b.x, b.y);
        }
        sY[r0*64 + col]       = sXr[r0*64 + col]       + d.x;
        sY[r0*64 + col+1]     = sXr[r0*64 + col+1]     + d.y;
        sY[(r0+8)*64 + col]   = sXr[(r0+8)*64 + col]   + d.z;
        sY[(r0+8)*64 + col+1] = sXr[(r0+8)*64 + col+1] + d.w;
    }
    __syncthreads();

    // LN
    {
        int r = t >> 4, l = t & 15;
        float4 v = *(const float4*)&sY[r*64 + l*4];
        float s  = v.x + v.y + v.z + v.w;
        float ss = v.x*v.x + v.y*v.y + v.z*v.z + v.w*v.w;
        #pragma unroll
        for (int o = 1; o < 16; o <<= 1) {
            s  += __shfl_xor_sync(0xffffffffu, s,  o, 16);
            ss += __shfl_xor_sync(0xffffffffu, ss, o, 16);
        }
        if (l == 0) {
            float m = s * (1.f/64.f);
            float var = ss * (1.f/64.f) - m*m;
            smean[r] = m; sinv[r] = rsqrtf(var + 1e-5f);
        }
    }
    __syncthreads();
    for (int i = t; i < 2048; i += 512) {
        int r = i >> 6, cc = i & 63;
        g_x2[(rbase + r)*64 + cc] = (sY[i] - smean[r]) * sinv[r] * ssg[cc] + ssb[cc];
    }
}

// ---------------- K6: FFN via tf32 MMA + residual + LN -> d_out --------------
__global__ __launch_bounds__(512) void ffn_kernel(
    const float* __restrict__ fb1, const float* __restrict__ fb2,
    const float* __restrict__ fg,  const float* __restrict__ fb,
    float* __restrict__ out)
{
    extern __shared__ float sm[];
    float* sA   = sm;               // X 32 x 68 tf32
    float* sH   = sA + 2176;        // H 32 x 260 tf32
    float* sXr  = sH + 8320;        // 32 x 64 fp32
    float* sY   = sXr + 2048;       // 32 x 64
    float* sb1  = sY + 2048;        // 256
    float* sb2  = sb1 + 256;        // 64
    float* sfg  = sb2 + 64;
    float* sfb  = sfg + 64;
    float* smean= sfb + 64;         // 32
    float* sinv = smean + 32;       // 32

    int t = threadIdx.x;
    if (t < 256) sb1[t] = fb1[t];
    if (t < 64) { sb2[t] = fb2[t]; sfg[t] = fg[t]; sfb[t] = fb[t]; }

    int rbase = blockIdx.x * 32;
    for (int idx = t; idx < 2048; idx += 512) {
        int c = idx & 63, r = idx >> 6;
        float v = g_x2[(rbase + r)*64 + c];
        sXr[r*64 + c] = v;
        sA[r*68 + c] = to_tf32(v);
    }
    __syncthreads();

    int w = t >> 5, lane = t & 31, g = lane >> 2, tg = lane & 3;

    // Stage1: H = gelu(X @ W1 + b1)
    {
        int mt = w >> 3, ng = w & 7;
        float4 d[4];
        #pragma unroll
        for (int i = 0; i < 4; i++) {
            int col = (ng*4 + i)*8 + 2*tg;
            d[i] = make_float4(sb1[col], sb1[col+1], sb1[col], sb1[col+1]);
        }
        #pragma unroll
        for (int kt = 0; kt < 8; kt++) {
            const float* Ab = sA + (mt*16)*68 + kt*8;
            float a0 = Ab[g*68 + tg],     a1 = Ab[(g+8)*68 + tg];
            float a2 = Ab[g*68 + tg + 4], a3 = Ab[(g+8)*68 + tg + 4];
            #pragma unroll
            for (int i = 0; i < 4; i++) {
                int nt = ng*4 + i;
                float2 b = __ldg((const float2*)&g_F1f[((((kt<<5) + nt)<<5) + lane)*2]);
                mma_tf32(d[i], a0, a1, a2, a3, b.x, b.y);
            }
        }
        int r0 = mt*16 + g;
        #pragma unroll
        for (int i = 0; i < 4; i++) {
            int col = (ng*4 + i)*8 + 2*tg;
            *(float2*)&sH[r0*260 + col]     = make_float2(to_tf32(gelu_f(d[i].x)), to_tf32(gelu_f(d[i].y)));
            *(float2*)&sH[(r0+8)*260 + col] = make_float2(to_tf32(gelu_f(d[i].z)), to_tf32(gelu_f(d[i].w)));
        }
    }
    __syncthreads();

    // Stage2: Y = X + H @ W2 + b2
    {
        int mt = w >> 3, nt = w & 7;
        int col = nt*8 + 2*tg;
        int r0 = mt*16 + g;
        float4 d = make_float4(sb2[col], sb2[col+1], sb2[col], sb2[col+1]);
        #pragma unroll
        for (int kt = 0; kt < 32; kt++) {
            const float* Ab = sH + (mt*16)*260 + kt*8;
            float a0 = Ab[g*260 + tg],     a1 = Ab[(g+8)*260 + tg];
            float a2 = Ab[g*260 + tg + 4], a3 = Ab[(g+8)*260 + tg + 4];
            float2 b = __ldg((const float2*)&g_F2f[((((kt<<3) + nt)<<5) + lane)*2]);
            mma_tf32(d, a0, a1, a2, a3, b.x, b.y);
        }
        sY[r0*64 + col]       = sXr[r0*64 + col]       + d.x;
        sY[r0*64 + col+1]     = sXr[r0*64 + col+1]     + d.y;
        sY[(r0+8)*64 + col]   = sXr[(r0+8)*64 + col]   + d.z;
        sY[(r0+8)*64 + col+1] = sXr[(r0+8)*64 + col+1] + d.w;
    }
    __syncthreads();

    // LN
    {
        int r = t >> 4, l = t & 15;
        float4 v = *(const float4*)&sY[r*64 + l*4];
        float s  = v.x + v.y + v.z + v.w;
        float ss = v.x*v.x + v.y*v.y + v.z*v.z + v.w*v.w;
        #pragma unroll
        for (int o = 1; o < 16; o <<= 1) {
            s  += __shfl_xor_sync(0xffffffffu, s,  o, 16);
            ss += __shfl_xor_sync(0xffffffffu, ss, o, 16);
        }
        if (l == 0) {
            float m = s * (1.f/64.f);
            float var = ss * (1.f/64.f) - m*m;
            smean[r] = m; sinv[r] = rsqrtf(var + 1e-5f);
        }
    }
    __syncthreads();
    for (int i = t; i < 2048; i += 512) {
        int r = i >> 6, cc = i & 63;
        out[(rbase + r)*64 + cc] = (sY[i] - smean[r]) * sinv[r] * sfg[cc] + sfb[cc];
    }
}

// ---------------- host launcher ---------------------------------------------
extern "C" void kernel_launch(void* const* d_in, const int* in_sizes, int n_in,
                              void* d_out, int out_size)
{
    (void)in_sizes; (void)n_in; (void)out_size;
    const float* x    = (const float*)d_in[0];
    const int*   ei   = (const int*)  d_in[1];
    const float* ea   = (const float*)d_in[2];
    const float* ipw  = (const float*)d_in[3];
    const float* ipb  = (const float*)d_in[4];
    const float* opw  = (const float*)d_in[5];
    const float* opb  = (const float*)d_in[6];
    const float* tng  = (const float*)d_in[7];
    const float* tnb  = (const float*)d_in[8];
    const float* ew1  = (const float*)d_in[9];
    const float* eb1  = (const float*)d_in[10];
    const float* ew2  = (const float*)d_in[11];
    const float* eb2  = (const float*)d_in[12];
    const float* mw1  = (const float*)d_in[13];
    const float* mb1  = (const float*)d_in[14];
    const float* mw2  = (const float*)d_in[15];
    const float* mb2  = (const float*)d_in[16];
    const float* uw1  = (const float*)d_in[17];
    const float* ub1  = (const float*)d_in[18];
    const float* uw2  = (const float*)d_in[19];
    const float* ub2  = (const float*)d_in[20];
    const float* sng  = (const float*)d_in[21];
    const float* snb  = (const float*)d_in[22];
    const float* fw1  = (const float*)d_in[23];
    const float* fb1  = (const float*)d_in[24];
    const float* fw2  = (const float*)d_in[25];
    const float* fb2  = (const float*)d_in[26];
    const float* fng  = (const float*)d_in[27];
    const float* fnb  = (const float*)d_in[28];
    float* out = (float*)d_out;

    const int SM_ATT = 25344 * 4;   // 101376
    const int SM_EE  = 4672 * 4;    // 18688
    const int SM_PQ  = (2176 + 8320) * 4;   // 41984
    const int SM_UPD = 15136 * 4;   // 60544
    const int SM_FFN = 15104 * 4;   // 60416
    cudaFuncSetAttribute(attn_kernel,     cudaFuncAttributeMaxDynamicSharedMemorySize, SM_ATT);
    cudaFuncSetAttribute(edge_emb_kernel, cudaFuncAttributeMaxDynamicSharedMemorySize, SM_EE);
    cudaFuncSetAttribute(pq_kernel,       cudaFuncAttributeMaxDynamicSharedMemorySize, SM_PQ);
    cudaFuncSetAttribute(update_kernel,   cudaFuncAttributeMaxDynamicSharedMemorySize, SM_UPD);
    cudaFuncSetAttribute(ffn_kernel,      cudaFuncAttributeMaxDynamicSharedMemorySize, SM_FFN);

    // position 4 gets captured by ncu -> pq (verifies coalesced-store delta)
    prep_kernel      <<<202, 512>>>(ipw, opw, mw1, mw2, uw1, uw2, fw1, fw2, ew2);
    attn_kernel      <<<2500, 512, SM_ATT>>>(x, ipb, opb, tng, tnb);
    csr_count_kernel <<<79, 256>>>(ei);
    pq_kernel        <<<5000, 512, SM_PQ>>>();
    csr_scan_kernel  <<<1, 1024>>>();
    csr_fill_kernel  <<<79, 256>>>(ei);
    edge_emb_kernel  <<<625, 512, SM_EE>>>(ea, ew1, eb1, eb2, mb1);
    update_kernel    <<<5000, 512, SM_UPD>>>(mb2, ub1, ub2, sng, snb);
    ffn_kernel       <<<5000, 512, SM_FFN>>>(fb1, fb2, fng, fnb, out);
}

// round 15
// speedup vs baseline: 1.2078x; 1.0143x over previous
#include <cuda_runtime.h>

// ---------------- problem constants ----------------
#define BB    2
#define SS    16
#define NN    5000
#define HH    64
#define EE    20000
#define BSS   (BB*SS)      // 32
#define BNN   (BB*NN)      // 10000
#define NROWS (BSS*NN)     // 160000

// ---------------- scratch (device globals) ----------------
__device__ __align__(16) float g_x1[NROWS*HH];
__device__ __align__(16) float g_x2[NROWS*HH];
__device__ __align__(16) float g_P [NROWS*128];
__device__ __align__(16) float g_R [EE*128];
__device__ int  g_cnt[NN];
__device__ int  g_cur[NN];
__device__ int  g_off[NN+1];
__device__ int2 g_epk[EE];     // (src, e) sorted by dst

// fragment-permuted weights (filled once per launch by prep_kernel)
__device__ __align__(16) float g_Wif [12288];   // in_proj 64x192, NT=24
__device__ __align__(16) float g_Wof [4096];    // out_proj 64x64, NT=8
__device__ __align__(16) float g_WPf [8192];    // Wa-Wb 64x128, NT=16 (pq)
__device__ __align__(16) float g_WQf [8192];    // Wb 64x128, NT=16 (update)
__device__ __align__(16) float g_W2f [8192];    // mw2 128x64, NT=8
__device__ __align__(16) float g_U1f [8192];    // uw1 128x64, NT=8
__device__ __align__(16) float g_U2f [4096];    // uw2 64x64, NT=8
__device__ __align__(16) float g_F1f [16384];   // fw1 64x256, NT=32
__device__ __align__(16) float g_F2f [16384];   // fw2 256x64, NT=8
__device__ __align__(16) float g_E2f [4096];    // ew2 64x64, NT=8
__device__ __align__(16) float g_Wcf [8192];    // mw1 rows 128..191 (64x128), NT=16

__device__ __forceinline__ float gelu_f(float v) {
    return 0.5f * v * (1.0f + erff(v * 0.70710678118654752f));
}

__device__ __forceinline__ float to_tf32(float x) {
    unsigned r;
    asm("cvt.rna.tf32.f32 %0, %1;" : "=r"(r) : "f"(x));
    return __uint_as_float(r);
}

__device__ __forceinline__ int fragidx(int k, int c, int NT) {
    int kt = k >> 3, kk = k & 7, j = kk >> 2, tg = kk & 3;
    int nt = c >> 3, gg = c & 7;
    return ((kt*NT + nt)*32 + (gg<<2) + tg)*2 + j;
}

// mma.m16n8k8 tf32: D(16x8) += A(16x8,row) * B(8x8,col)
__device__ __forceinline__ void mma_tf32(float4& d,
    float a0, float a1, float a2, float a3, float b0, float b1)
{
    asm volatile(
      "mma.sync.aligned.m16n8k8.row.col.f32.tf32.tf32.f32 "
      "{%0,%1,%2,%3},{%4,%5,%6,%7},{%8,%9},{%0,%1,%2,%3};\n"
      : "+f"(d.x), "+f"(d.y), "+f"(d.z), "+f"(d.w)
      : "r"(__float_as_uint(a0)), "r"(__float_as_uint(a1)),
        "r"(__float_as_uint(a2)), "r"(__float_as_uint(a3)),
        "r"(__float_as_uint(b0)), "r"(__float_as_uint(b1)));
}

// ---------------- prep: permute weights + zero CSR counters -----------------
__global__ void prep_kernel(
    const float* __restrict__ Wi,  const float* __restrict__ Wo,
    const float* __restrict__ mw1, const float* __restrict__ mw2,
    const float* __restrict__ uw1, const float* __restrict__ uw2,
    const float* __restrict__ fw1, const float* __restrict__ fw2,
    const float* __restrict__ ew2)
{
    int i = blockIdx.x * 512 + threadIdx.x;   // grid 202*512
    if (i < 12288) {                              // Wi 64x192
        int k = i / 192, c = i % 192;
        g_Wif[fragidx(k, c, 24)] = to_tf32(Wi[i]);
    } else if (i < 16384) {                       // Wo 64x64
        int idx = i - 12288, k = idx >> 6, c = idx & 63;
        g_Wof[fragidx(k, c, 8)] = to_tf32(Wo[idx]);
    } else if (i < 24576) {                       // WP = Wa-Wb 64x128
        int idx = i - 16384, k = idx >> 7, c = idx & 127;
        g_WPf[fragidx(k, c, 16)] = to_tf32(mw1[k*128 + c] - mw1[(64+k)*128 + c]);
    } else if (i < 32768) {                       // WQ = Wb 64x128
        int idx = i - 24576, k = idx >> 7, c = idx & 127;
        g_WQf[fragidx(k, c, 16)] = to_tf32(mw1[(64+k)*128 + c]);
    } else if (i < 40960) {                       // mw2 128x64
        int idx = i - 32768, k = idx >> 6, c = idx & 63;
        g_W2f[fragidx(k, c, 8)] = to_tf32(mw2[idx]);
    } else if (i < 49152) {                       // uw1 128x64
        int idx = i - 40960, k = idx >> 6, c = idx & 63;
        g_U1f[fragidx(k, c, 8)] = to_tf32(uw1[idx]);
    } else if (i < 53248) {                       // uw2 64x64
        int idx = i - 49152, k = idx >> 6, c = idx & 63;
        g_U2f[fragidx(k, c, 8)] = to_tf32(uw2[idx]);
    } else if (i < 69632) {                       // fw1 64x256
        int idx = i - 53248, k = idx >> 8, c = idx & 255;
        g_F1f[fragidx(k, c, 32)] = to_tf32(fw1[idx]);
    } else if (i < 86016) {                       // fw2 256x64
        int idx = i - 69632, k = idx >> 6, c = idx & 63;
        g_F2f[fragidx(k, c, 8)] = to_tf32(fw2[idx]);
    } else if (i < 90112) {                       // ew2 64x64
        int idx = i - 86016, k = idx >> 6, c = idx & 63;
        g_E2f[fragidx(k, c, 8)] = to_tf32(ew2[idx]);
    } else if (i < 98304) {                       // Wc = mw1 rows 128..191, 64x128
        int idx = i - 90112, k = idx >> 7, c = idx & 127;
        g_Wcf[fragidx(k, c, 16)] = to_tf32(mw1[(128 + k)*128 + c]);
    } else if (i < 98304 + NN) {                  // zero CSR counters
        g_cnt[i - 98304] = 0;
    }
}

// ---------------- CSR build ----------------
__global__ void csr_count_kernel(const int* __restrict__ ei) {
    int e = blockIdx.x * blockDim.x + threadIdx.x;
    if (e < EE) atomicAdd(&g_cnt[ei[EE + e]], 1);
}
__global__ void csr_scan_kernel() {
    __shared__ int sbuf[1024];
    __shared__ int scarry;
    int t = threadIdx.x;
    if (t == 0) scarry = 0;
    __syncthreads();
    for (int ch = 0; ch < 5; ch++) {
        int idx = ch * 1024 + t;
        int v = (idx < NN) ? g_cnt[idx] : 0;
        sbuf[t] = v; __syncthreads();
        for (int o = 1; o < 1024; o <<= 1) {
            int x = (t >= o) ? sbuf[t - o] : 0;
            __syncthreads();
            sbuf[t] += x;
            __syncthreads();
        }
        int incl = sbuf[t];
        int base = scarry;
        if (idx < NN) { int off = base + incl - v; g_off[idx] = off; g_cur[idx] = off; }
        __syncthreads();
        if (t == 1023) scarry = base + sbuf[1023];
        __syncthreads();
    }
    if (t == 0) g_off[NN] = scarry;
}
__global__ void csr_fill_kernel(const int* __restrict__ ei) {
    int e = blockIdx.x * blockDim.x + threadIdx.x;
    if (e < EE) {
        int dst = ei[EE + e];
        int pos = atomicAdd(&g_cur[dst], 1);
        g_epk[pos] = make_int2(ei[e], e);
    }
}

// ---------------- K1: temporal attention via tf32 MMA + residual + LN -------
__global__ __launch_bounds__(512, 2) void attn_kernel(
    const float* __restrict__ x,
    const float* __restrict__ bi, const float* __restrict__ bo,
    const float* __restrict__ tg_, const float* __restrict__ tb_)
{
    extern __shared__ float sm[];
    float* sbi  = sm;            // 192
    float* sbo  = sbi + 192;     // 64
    float* stg  = sbo + 64;      // 64
    float* stb  = stg + 64;      // 64
    float* sX   = stb + 64;      // 64x68 tf32 (also residual source)
    float* sqkvT= sX + 4352;     // [seq<4][j<192][s<16] pad20 = 15360
    float* saoT = sqkvT + 15360; // [seq<4][d<64][q<16] pad20 = 5120
    float* sY   = sqkvT;         // alias: sqkvT dead after softmax
    float* smean= saoT + 5120;   // 64
    float* sinv = smean + 64;    // 64

    int t = threadIdx.x;
    if (t < 192) sbi[t] = bi[t];
    if (t < 64) { sbo[t] = bo[t]; stg[t] = tg_[t]; stb[t] = tb_[t]; }

    int bn0 = blockIdx.x * 4;
    for (int idx = t; idx < 4096; idx += 512) {
        int row = idx >> 6, c = idx & 63;
        int seq = row >> 4, s = row & 15;
        int bn = bn0 + seq;
        int b = bn / NN, n = bn % NN;
        sX[row*68 + c] = to_tf32(x[((b*SS + s)*NN + n)*HH + c]);
    }
    __syncthreads();

    int w = t >> 5, lane = t & 31, g = lane >> 2, tg = lane & 3;

    // qkv = X @ Wi + bi : M=64, N=192, K=64. warp: mt=w>>2, 6 n-tiles
    {
        int mt = w >> 2, ng = w & 3;
        float4 d[6];
        #pragma unroll
        for (int i = 0; i < 6; i++) {
            int col = (ng*6 + i)*8 + 2*tg;
            d[i] = make_float4(sbi[col], sbi[col+1], sbi[col], sbi[col+1]);
        }
        #pragma unroll
        for (int kt = 0; kt < 8; kt++) {
            const float* Ab = sX + (mt*16)*68 + kt*8;
            float a0 = Ab[g*68 + tg],     a1 = Ab[(g+8)*68 + tg];
            float a2 = Ab[g*68 + tg + 4], a3 = Ab[(g+8)*68 + tg + 4];
            #pragma unroll
            for (int i = 0; i < 6; i++) {
                int nt = ng*6 + i;
                float2 b = __ldg((const float2*)&g_Wif[((kt*24 + nt)*32 + lane)*2]);
                mma_tf32(d[i], a0, a1, a2, a3, b.x, b.y);
            }
        }
        #pragma unroll
        for (int i = 0; i < 6; i++) {
            int col = (ng*6 + i)*8 + 2*tg;
            float* base = sqkvT + (mt*192 + col)*20;
            base[g]        = d[i].x;
            base[20 + g]   = d[i].y;
            base[g + 8]    = d[i].z;
            base[20 + g+8] = d[i].w;
        }
    }
    __syncthreads();

    // attention core (exact fp32): thread = (seq, head, q), 256 active
    if (t < 256) {
        int seq = t >> 6, h = (t >> 4) & 3, q = t & 15;
        const float* Qb = sqkvT + (seq*192 + h*16)*20;
        const float* Kb = Qb + 64*20;
        const float* Vb = Qb + 128*20;
        float sc[16];
        #pragma unroll
        for (int k = 0; k < 16; k++) sc[k] = 0.f;
        #pragma unroll
        for (int d = 0; d < 16; d++) {
            float qv = Qb[d*20 + q];
            const float4* kk = (const float4*)(Kb + d*20);
            float4 k0 = kk[0], k1 = kk[1], k2 = kk[2], k3 = kk[3];
            sc[0]+=qv*k0.x; sc[1]+=qv*k0.y; sc[2]+=qv*k0.z; sc[3]+=qv*k0.w;
            sc[4]+=qv*k1.x; sc[5]+=qv*k1.y; sc[6]+=qv*k1.z; sc[7]+=qv*k1.w;
            sc[8]+=qv*k2.x; sc[9]+=qv*k2.y; sc[10]+=qv*k2.z; sc[11]+=qv*k2.w;
            sc[12]+=qv*k3.x; sc[13]+=qv*k3.y; sc[14]+=qv*k3.z; sc[15]+=qv*k3.w;
        }
        float mx = -1e30f;
        #pragma unroll
        for (int k = 0; k < 16; k++) { sc[k] *= 0.25f; mx = fmaxf(mx, sc[k]); }
        float den = 0.f;
        #pragma unroll
        for (int k = 0; k < 16; k++) { sc[k] = expf(sc[k] - mx); den += sc[k]; }
        float inv = 1.f / den;
        #pragma unroll
        for (int d = 0; d < 16; d++) {
            const float4* vv = (const float4*)(Vb + d*20);
            float4 v0 = vv[0], v1 = vv[1], v2 = vv[2], v3 = vv[3];
            float o = sc[0]*v0.x + sc[1]*v0.y + sc[2]*v0.z + sc[3]*v0.w
                    + sc[4]*v1.x + sc[5]*v1.y + sc[6]*v1.z + sc[7]*v1.w
                    + sc[8]*v2.x + sc[9]*v2.y + sc[10]*v2.z + sc[11]*v2.w
                    + sc[12]*v3.x + sc[13]*v3.y + sc[14]*v3.z + sc[15]*v3.w;
            saoT[(seq*64 + h*16 + d)*20 + q] = to_tf32(o * inv);
        }
    }
    __syncthreads();

    // out-proj: Y = X + AO @ Wo + bo
    {
        int mt = w >> 2, np = w & 3;
        float4 d[2];
        #pragma unroll
        for (int i = 0; i < 2; i++) {
            int col = (np*2 + i)*8 + 2*tg;
            d[i] = make_float4(sbo[col], sbo[col+1], sbo[col], sbo[col+1]);
        }
        #pragma unroll
        for (int kt = 0; kt < 8; kt++) {
            const float* Ab = saoT + (mt*64 + kt*8)*20;
            float a0 = Ab[tg*20 + g],       a1 = Ab[tg*20 + g + 8];
            float a2 = Ab[(tg+4)*20 + g],   a3 = Ab[(tg+4)*20 + g + 8];
            #pragma unroll
            for (int i = 0; i < 2; i++) {
                int nt = np*2 + i;
                float2 b = __ldg((const float2*)&g_Wof[((((kt<<3) + nt)<<5) + lane)*2]);
                mma_tf32(d[i], a0, a1, a2, a3, b.x, b.y);
            }
        }
        int r0 = mt*16 + g;
        #pragma unroll
        for (int i = 0; i < 2; i++) {
            int col = (np*2 + i)*8 + 2*tg;
            sY[r0*64 + col]       = sX[r0*68 + col]       + d[i].x;
            sY[r0*64 + col+1]     = sX[r0*68 + col+1]     + d[i].y;
            sY[(r0+8)*64 + col]   = sX[(r0+8)*68 + col]   + d[i].z;
            sY[(r0+8)*64 + col+1] = sX[(r0+8)*68 + col+1] + d[i].w;
        }
    }
    __syncthreads();

    // LN: 64 rows, 8 lanes per row
    {
        int r = t >> 3, l = t & 7;
        float4 v1 = *(const float4*)&sY[r*64 + l*8];
        float4 v2 = *(const float4*)&sY[r*64 + l*8 + 4];
        float s  = v1.x+v1.y+v1.z+v1.w + v2.x+v2.y+v2.z+v2.w;
        float ss = v1.x*v1.x+v1.y*v1.y+v1.z*v1.z+v1.w*v1.w
                 + v2.x*v2.x+v2.y*v2.y+v2.z*v2.z+v2.w*v2.w;
        #pragma unroll
        for (int o = 1; o < 8; o <<= 1) {
            s  += __shfl_xor_sync(0xffffffffu, s,  o, 8);
            ss += __shfl_xor_sync(0xffffffffu, ss, o, 8);
        }
        if (l == 0) {
            float m = s * (1.f/64.f);
            float var = ss * (1.f/64.f) - m*m;
            smean[r] = m; sinv[r] = rsqrtf(var + 1e-5f);
        }
    }
    __syncthreads();
    for (int idx = t; idx < 4096; idx += 512) {
        int row = idx >> 6, c = idx & 63;
        int seq = row >> 4, s = row & 15;
        int bn = bn0 + seq;
        int b = bn / NN, n = bn % NN;
        g_x1[((b*SS + s)*NN + n)*HH + c] =
            (sY[idx] - smean[row]) * sinv[row] * stg[c] + stb[c];
    }
}

// ---------------- K2: edge embedding -> R via tf32 MMA ----------------------
__global__ __launch_bounds__(512) void edge_emb_kernel(
    const float* __restrict__ ea,
    const float* __restrict__ ew1, const float* __restrict__ eb1,
    const float* __restrict__ eb2, const float* __restrict__ mb1)
{
    extern __shared__ float sm[];
    float* sE0  = sm;          // 32x68 tf32
    float* sE2  = sm + 2176;   // 32x68 tf32
    float* sew1 = sm + 4352;   // 64
    float* seb1 = sew1 + 64;   // 64
    float* seb2 = seb1 + 64;   // 64
    float* smb1 = seb2 + 64;   // 128

    int t = threadIdx.x;
    if (t < 64) { sew1[t] = ew1[t]; seb1[t] = eb1[t]; seb2[t] = eb2[t]; }
    else if (t < 192) smb1[t-64] = mb1[t-64];
    int e0 = blockIdx.x * 32;
    __syncthreads();

    // Stage0: E0 = gelu(ea * ew1 + eb1) per edge-row
    for (int idx = t; idx < 2048; idx += 512) {
        int r = idx >> 6, c = idx & 63;
        sE0[r*68 + c] = to_tf32(gelu_f(__ldg(&ea[e0 + r]) * sew1[c] + seb1[c]));
    }
    __syncthreads();

    int w = t >> 5, lane = t & 31, g = lane >> 2, tg = lane & 3;

    // Stage1: E2 = E0 @ ew2 + eb2 : M=32, N=64, K=64
    {
        int mt = w >> 3, nt = w & 7;
        int col = nt*8 + 2*tg;
        int r0 = mt*16 + g;
        float4 d = make_float4(seb2[col], seb2[col+1], seb2[col], seb2[col+1]);
        #pragma unroll
        for (int kt = 0; kt < 8; kt++) {
            const float* Ab = sE0 + (mt*16)*68 + kt*8;
            float a0 = Ab[g*68 + tg],     a1 = Ab[(g+8)*68 + tg];
            float a2 = Ab[g*68 + tg + 4], a3 = Ab[(g+8)*68 + tg + 4];
            float2 b = __ldg((const float2*)&g_E2f[((((kt<<3) + nt)<<5) + lane)*2]);
            mma_tf32(d, a0, a1, a2, a3, b.x, b.y);
        }
        *(float2*)&sE2[r0*68 + col]     = make_float2(to_tf32(d.x), to_tf32(d.y));
        *(float2*)&sE2[(r0+8)*68 + col] = make_float2(to_tf32(d.z), to_tf32(d.w));
    }
    __syncthreads();

    // Stage2: R = E2 @ Wc + mb1 : M=32, N=128, K=64 (warp does 2 n-tiles)
    {
        int mt = w >> 3, ng = w & 7;
        float4 d[2];
        #pragma unroll
        for (int i = 0; i < 2; i++) {
            int col = (ng*2 + i)*8 + 2*tg;
            d[i] = make_float4(smb1[col], smb1[col+1], smb1[col], smb1[col+1]);
        }
        #pragma unroll
        for (int kt = 0; kt < 8; kt++) {
            const float* Ab = sE2 + (mt*16)*68 + kt*8;
            float a0 = Ab[g*68 + tg],     a1 = Ab[(g+8)*68 + tg];
            float a2 = Ab[g*68 + tg + 4], a3 = Ab[(g+8)*68 + tg + 4];
            #pragma unroll
            for (int i = 0; i < 2; i++) {
                int nt = ng*2 + i;
                float2 b = __ldg((const float2*)&g_Wcf[((kt*16 + nt)*32 + lane)*2]);
                mma_tf32(d[i], a0, a1, a2, a3, b.x, b.y);
            }
        }
        int r0 = mt*16 + g;
        #pragma unroll
        for (int i = 0; i < 2; i++) {
            int col = (ng*2 + i)*8 + 2*tg;
            *(float2*)&g_R[(e0 + r0)*128 + col]     = make_float2(d[i].x, d[i].y);
            *(float2*)&g_R[(e0 + r0 + 8)*128 + col] = make_float2(d[i].z, d[i].w);
        }
    }
}

// ---------------- K3: P node GEMM via tf32 MMA (smem-staged stores) ---------
// P = x1 @ (Wa - Wb) : M=32, N=128, K=64. Q is computed inside update_kernel.
__global__ __launch_bounds__(512) void pq_kernel()
{
    extern __shared__ float sm[];
    float* sA   = sm;          // 32 x 68 (tf32)
    float* sOut = sm + 2176;   // 32 x 132 (fp32 results, padded)

    int t = threadIdx.x;
    int rbase = blockIdx.x * 32;
    for (int idx = t; idx < 2048; idx += 512) {
        int r = idx >> 6, c = idx & 63;
        sA[r*68 + c] = to_tf32(g_x1[(rbase + r)*64 + c]);
    }
    __syncthreads();

    int w = t >> 5, lane = t & 31, g = lane >> 2, tg = lane & 3;
    int mt = w >> 3, ng = w & 7;
    float4 d[2];
    #pragma unroll
    for (int i = 0; i < 2; i++) d[i] = make_float4(0.f, 0.f, 0.f, 0.f);

    #pragma unroll
    for (int kt = 0; kt < 8; kt++) {
        const float* Ab = sA + (mt*16)*68 + kt*8;
        float a0 = Ab[g*68 + tg],     a1 = Ab[(g+8)*68 + tg];
        float a2 = Ab[g*68 + tg + 4], a3 = Ab[(g+8)*68 + tg + 4];
        #pragma unroll
        for (int i = 0; i < 2; i++) {
            int nt = ng*2 + i;
            float2 b = __ldg((const float2*)&g_WPf[((kt*16 + nt)*32 + lane)*2]);
            mma_tf32(d[i], a0, a1, a2, a3, b.x, b.y);
        }
    }

    // stage results in smem
    {
        int r0 = mt*16 + g;
        #pragma unroll
        for (int i = 0; i < 2; i++) {
            int col = (ng*2 + i)*8 + 2*tg;
            *(float2*)&sOut[r0*132 + col]     = make_float2(d[i].x, d[i].y);
            *(float2*)&sOut[(r0+8)*132 + col] = make_float2(d[i].z, d[i].w);
        }
    }
    __syncthreads();

    // coalesced writeout
    for (int idx = t; idx < 4096; idx += 512) {
        int r = idx >> 7, c = idx & 127;
        g_P[(rbase + r)*128 + c] = sOut[r*132 + c];
    }
}

// ---------------- K5: fused Q-GEMM + gather + update MLP + LN ---------------
// Block = 32 consecutive (bs,n) rows. Q computed in-kernel from x1 (identical
// math to the old pq Q-half), gather reads Q from smem; warp gathers 2 rows.
__global__ __launch_bounds__(512) void update_kernel(
    const float* __restrict__ mb2, const float* __restrict__ ub1,
    const float* __restrict__ ub2,
    const float* __restrict__ sg,  const float* __restrict__ sb)
{
    extern __shared__ float sm[];
    float* sG   = sm;               // 32 x 132 tf32
    float* sUin = sG + 4224;        // 32 x 132 tf32
    float* sHid = sUin + 4224;      // 32 x 68 tf32
    float* sXr  = sHid + 2176;      // 32 x 64 fp32
    float* sY   = sXr + 2048;       // 32 x 64
    float* smb2 = sY + 2048;        // 64
    float* sub1 = smb2 + 64;
    float* sub2 = sub1 + 64;
    float* ssg  = sub2 + 64;
    float* ssb  = ssg + 64;
    float* sdeg = ssb + 64;         // 32
    float* smean= sdeg + 32;        // 32
    float* sinv = smean + 32;       // 32
    float* sQ   = sinv + 32;        // 32 x 132 fp32 (4224)

    int t = threadIdx.x;
    if (t < 64) { smb2[t] = mb2[t]; sub1[t] = ub1[t]; sub2[t] = ub2[t]; ssg[t] = sg[t]; ssb[t] = sb[t]; }

    int rbase = blockIdx.x * 32;
    for (int idx = t; idx < 2048; idx += 512) {
        int c = idx & 63, r = idx >> 6;
        float v = g_x1[(rbase + r)*64 + c];
        sXr[r*64 + c] = v;
        sUin[r*132 + c] = to_tf32(v);
    }
    __syncthreads();

    int w = t >> 5, lane = t & 31;
    int g = lane >> 2, tg = lane & 3;

    // Stage Q: Q = X @ Wb : M=32, N=128, K=64 (warp does 2 n-tiles)
    {
        int mt = w >> 3, ng = w & 7;
        float4 d[2];
        #pragma unroll
        for (int i = 0; i < 2; i++) d[i] = make_float4(0.f, 0.f, 0.f, 0.f);
        #pragma unroll
        for (int kt = 0; kt < 8; kt++) {
            const float* Ab = sUin + (mt*16)*132 + kt*8;
            float a0 = Ab[g*132 + tg],     a1 = Ab[(g+8)*132 + tg];
            float a2 = Ab[g*132 + tg + 4], a3 = Ab[(g+8)*132 + tg + 4];
            #pragma unroll
            for (int i = 0; i < 2; i++) {
                int nt = ng*2 + i;
                float2 b = __ldg((const float2*)&g_WQf[((kt*16 + nt)*32 + lane)*2]);
                mma_tf32(d[i], a0, a1, a2, a3, b.x, b.y);
            }
        }
        int r0 = mt*16 + g;
        #pragma unroll
        for (int i = 0; i < 2; i++) {
            int col = (ng*2 + i)*8 + 2*tg;
            *(float2*)&sQ[r0*132 + col]     = make_float2(d[i].x, d[i].y);
            *(float2*)&sQ[(r0+8)*132 + col] = make_float2(d[i].z, d[i].w);
        }
    }
    __syncthreads();

    // fused CSR gather: warp w accumulates rows w*2, w*2+1 into sG (tf32)
    {
        const float4* P4 = (const float4*)g_P;
        const float4* R4 = (const float4*)g_R;
        #pragma unroll
        for (int j = 0; j < 2; j++) {
            int lr = w*2 + j;                 // local row 0..31
            int row = rbase + lr;
            int bs = row / NN, n = row - bs*NN;
            float4 q = *(const float4*)&sQ[lr*132 + lane*4];
            float4 acc = make_float4(0.f, 0.f, 0.f, 0.f);
            int s = __ldg(&g_off[n]), e = __ldg(&g_off[n+1]);
            if (s < e) {
                int2 pe = __ldg(&g_epk[s]);
                for (int k = s; k < e; k++) {
                    int2 pen = (k + 1 < e) ? __ldg(&g_epk[k+1]) : pe;
                    float4 p = __ldg(P4 + (bs*NN + pe.x)*32 + lane);
                    float4 r = __ldg(R4 + pe.y*32 + lane);
                    acc.x += gelu_f(p.x + q.x + r.x);
                    acc.y += gelu_f(p.y + q.y + r.y);
                    acc.z += gelu_f(p.z + q.z + r.z);
                    acc.w += gelu_f(p.w + q.w + r.w);
                    pe = pen;
                }
            }
            *(float4*)&sG[lr*132 + lane*4] =
                make_float4(to_tf32(acc.x), to_tf32(acc.y),
                            to_tf32(acc.z), to_tf32(acc.w));
            if (lane == 0) sdeg[lr] = (float)(e - s);
        }
    }
    __syncthreads();

    int mt = w >> 3, nt = w & 7;
    int col = nt*8 + 2*tg;
    int r0 = mt*16 + g;

    // Stage0: aggr = G @ mw2 + deg*mb2
    {
        float4 d = make_float4(sdeg[r0]*smb2[col],   sdeg[r0]*smb2[col+1],
                               sdeg[r0+8]*smb2[col], sdeg[r0+8]*smb2[col+1]);
        #pragma unroll
        for (int kt = 0; kt < 16; kt++) {
            const float* Ab = sG + (mt*16)*132 + kt*8;
            float a0 = Ab[g*132 + tg],     a1 = Ab[(g+8)*132 + tg];
            float a2 = Ab[g*132 + tg + 4], a3 = Ab[(g+8)*132 + tg + 4];
            float2 b = __ldg((const float2*)&g_W2f[((((kt<<3) + nt)<<5) + lane)*2]);
            mma_tf32(d, a0, a1, a2, a3, b.x, b.y);
        }
        *(float2*)&sUin[r0*132 + 64 + col]     = make_float2(to_tf32(d.x), to_tf32(d.y));
        *(float2*)&sUin[(r0+8)*132 + 64 + col] = make_float2(to_tf32(d.z), to_tf32(d.w));
    }
    __syncthreads();

    // Stage1: hid = gelu(Uin @ uw1 + ub1)
    {
        float4 d = make_float4(sub1[col], sub1[col+1], sub1[col], sub1[col+1]);
        #pragma unroll
        for (int kt = 0; kt < 16; kt++) {
            const float* Ab = sUin + (mt*16)*132 + kt*8;
            float a0 = Ab[g*132 + tg],     a1 = Ab[(g+8)*132 + tg];
            float a2 = Ab[g*132 + tg + 4], a3 = Ab[(g+8)*132 + tg + 4];
            float2 b = __ldg((const float2*)&g_U1f[((((kt<<3) + nt)<<5) + lane)*2]);
            mma_tf32(d, a0, a1, a2, a3, b.x, b.y);
        }
        *(float2*)&sHid[r0*68 + col]     = make_float2(to_tf32(gelu_f(d.x)), to_tf32(gelu_f(d.y)));
        *(float2*)&sHid[(r0+8)*68 + col] = make_float2(to_tf32(gelu_f(d.z)), to_tf32(gelu_f(d.w)));
    }
    __syncthreads();

    // Stage2: y = xs + hid @ uw2 + ub2
    {
        float4 d = make_float4(sub2[col], sub2[col+1], sub2[col], sub2[col+1]);
        #pragma unroll
        for (int kt = 0; kt < 8; kt++) {
            const float* Ab = sHid + (mt*16)*68 + kt*8;
            float a0 = Ab[g*68 + tg],     a1 = Ab[(g+8)*68 + tg];
            float a2 = Ab[g*68 + tg + 4], a3 = Ab[(g+8)*68 + tg + 4];
            float2 b = __ldg((const float2*)&g_U2f[((((kt<<3) + nt)<<5) + lane)*2]);
            mma_tf32(d, a0, a1, a2, a3, b.x, b.y);
        }
        sY[r0*64 + col]       = sXr[r0*64 + col]       + d.x;
        sY[r0*64 + col+1]     = sXr[r0*64 + col+1]     + d.y;
        sY[(r0+8)*64 + col]   = sXr[(r0+8)*64 + col]   + d.z;
        sY[(r0+8)*64 + col+1] = sXr[(r0+8)*64 + col+1] + d.w;
    }
    __syncthreads();

    // LN
    {
        int r = t >> 4, l = t & 15;
        float4 v = *(const float4*)&sY[r*64 + l*4];
        float s  = v.x + v.y + v.z + v.w;
        float ss = v.x*v.x + v.y*v.y + v.z*v.z + v.w*v.w;
        #pragma unroll
        for (int o = 1; o < 16; o <<= 1) {
            s  += __shfl_xor_sync(0xffffffffu, s,  o, 16);
            ss += __shfl_xor_sync(0xffffffffu, ss, o, 16);
        }
        if (l == 0) {
            float m = s * (1.f/64.f);
            float var = ss * (1.f/64.f) - m*m;
            smean[r] = m; sinv[r] = rsqrtf(var + 1e-5f);
        }
    }
    __syncthreads();
    for (int i = t; i < 2048; i += 512) {
        int r = i >> 6, cc = i & 63;
        g_x2[(rbase + r)*64 + cc] = (sY[i] - smean[r]) * sinv[r] * ssg[cc] + ssb[cc];
    }
}

// ---------------- K6: FFN via tf32 MMA + residual + LN -> d_out --------------
__global__ __launch_bounds__(512) void ffn_kernel(
    const float* __restrict__ fb1, const float* __restrict__ fb2,
    const float* __restrict__ fg,  const float* __restrict__ fb,
    float* __restrict__ out)
{
    extern __shared__ float sm[];
    float* sA   = sm;               // X 32 x 68 tf32
    float* sH   = sA + 2176;        // H 32 x 260 tf32
    float* sXr  = sH + 8320;        // 32 x 64 fp32
    float* sY   = sXr + 2048;       // 32 x 64
    float* sb1  = sY + 2048;        // 256
    float* sb2  = sb1 + 256;        // 64
    float* sfg  = sb2 + 64;
    float* sfb  = sfg + 64;
    float* smean= sfb + 64;         // 32
    float* sinv = smean + 32;       // 32

    int t = threadIdx.x;
    if (t < 256) sb1[t] = fb1[t];
    if (t < 64) { sb2[t] = fb2[t]; sfg[t] = fg[t]; sfb[t] = fb[t]; }

    int rbase = blockIdx.x * 32;
    for (int idx = t; idx < 2048; idx += 512) {
        int c = idx & 63, r = idx >> 6;
        float v = g_x2[(rbase + r)*64 + c];
        sXr[r*64 + c] = v;
        sA[r*68 + c] = to_tf32(v);
    }
    __syncthreads();

    int w = t >> 5, lane = t & 31, g = lane >> 2, tg = lane & 3;

    // Stage1: H = gelu(X @ W1 + b1)
    {
        int mt = w >> 3, ng = w & 7;
        float4 d[4];
        #pragma unroll
        for (int i = 0; i < 4; i++) {
            int col = (ng*4 + i)*8 + 2*tg;
            d[i] = make_float4(sb1[col], sb1[col+1], sb1[col], sb1[col+1]);
        }
        #pragma unroll
        for (int kt = 0; kt < 8; kt++) {
            const float* Ab = sA + (mt*16)*68 + kt*8;
            float a0 = Ab[g*68 + tg],     a1 = Ab[(g+8)*68 + tg];
            float a2 = Ab[g*68 + tg + 4], a3 = Ab[(g+8)*68 + tg + 4];
            #pragma unroll
            for (int i = 0; i < 4; i++) {
                int nt = ng*4 + i;
                float2 b = __ldg((const float2*)&g_F1f[((((kt<<5) + nt)<<5) + lane)*2]);
                mma_tf32(d[i], a0, a1, a2, a3, b.x, b.y);
            }
        }
        int r0 = mt*16 + g;
        #pragma unroll
        for (int i = 0; i < 4; i++) {
            int col = (ng*4 + i)*8 + 2*tg;
            *(float2*)&sH[r0*260 + col]     = make_float2(to_tf32(gelu_f(d[i].x)), to_tf32(gelu_f(d[i].y)));
            *(float2*)&sH[(r0+8)*260 + col] = make_float2(to_tf32(gelu_f(d[i].z)), to_tf32(gelu_f(d[i].w)));
        }
    }
    __syncthreads();

    // Stage2: Y = X + H @ W2 + b2
    {
        int mt = w >> 3, nt = w & 7;
        int col = nt*8 + 2*tg;
        int r0 = mt*16 + g;
        float4 d = make_float4(sb2[col], sb2[col+1], sb2[col], sb2[col+1]);
        #pragma unroll
        for (int kt = 0; kt < 32; kt++) {
            const float* Ab = sH + (mt*16)*260 + kt*8;
            float a0 = Ab[g*260 + tg],     a1 = Ab[(g+8)*260 + tg];
            float a2 = Ab[g*260 + tg + 4], a3 = Ab[(g+8)*260 + tg + 4];
            float2 b = __ldg((const float2*)&g_F2f[((((kt<<3) + nt)<<5) + lane)*2]);
            mma_tf32(d, a0, a1, a2, a3, b.x, b.y);
        }
        sY[r0*64 + col]       = sXr[r0*64 + col]       + d.x;
        sY[r0*64 + col+1]     = sXr[r0*64 + col+1]     + d.y;
        sY[(r0+8)*64 + col]   = sXr[(r0+8)*64 + col]   + d.z;
        sY[(r0+8)*64 + col+1] = sXr[(r0+8)*64 + col+1] + d.w;
    }
    __syncthreads();

    // LN
    {
        int r = t >> 4, l = t & 15;
        float4 v = *(const float4*)&sY[r*64 + l*4];
        float s  = v.x + v.y + v.z + v.w;
        float ss = v.x*v.x + v.y*v.y + v.z*v.z + v.w*v.w;
        #pragma unroll
        for (int o = 1; o < 16; o <<= 1) {
            s  += __shfl_xor_sync(0xffffffffu, s,  o, 16);
            ss += __shfl_xor_sync(0xffffffffu, ss, o, 16);
        }
        if (l == 0) {
            float m = s * (1.f/64.f);
            float var = ss * (1.f/64.f) - m*m;
            smean[r] = m; sinv[r] = rsqrtf(var + 1e-5f);
        }
    }
    __syncthreads();
    for (int i = t; i < 2048; i += 512) {
        int r = i >> 6, cc = i & 63;
        out[(rbase + r)*64 + cc] = (sY[i] - smean[r]) * sinv[r] * sfg[cc] + sfb[cc];
    }
}

// ---------------- host launcher ---------------------------------------------
extern "C" void kernel_launch(void* const* d_in, const int* in_sizes, int n_in,
                              void* d_out, int out_size)
{
    (void)in_sizes; (void)n_in; (void)out_size;
    const float* x    = (const float*)d_in[0];
    const int*   ei   = (const int*)  d_in[1];
    const float* ea   = (const float*)d_in[2];
    const float* ipw  = (const float*)d_in[3];
    const float* ipb  = (const float*)d_in[4];
    const float* opw  = (const float*)d_in[5];
    const float* opb  = (const float*)d_in[6];
    const float* tng  = (const float*)d_in[7];
    const float* tnb  = (const float*)d_in[8];
    const float* ew1  = (const float*)d_in[9];
    const float* eb1  = (const float*)d_in[10];
    const float* ew2  = (const float*)d_in[11];
    const float* eb2  = (const float*)d_in[12];
    const float* mw1  = (const float*)d_in[13];
    const float* mb1  = (const float*)d_in[14];
    const float* mw2  = (const float*)d_in[15];
    const float* mb2  = (const float*)d_in[16];
    const float* uw1  = (const float*)d_in[17];
    const float* ub1  = (const float*)d_in[18];
    const float* uw2  = (const float*)d_in[19];
    const float* ub2  = (const float*)d_in[20];
    const float* sng  = (const float*)d_in[21];
    const float* snb  = (const float*)d_in[22];
    const float* fw1  = (const float*)d_in[23];
    const float* fb1  = (const float*)d_in[24];
    const float* fw2  = (const float*)d_in[25];
    const float* fb2  = (const float*)d_in[26];
    const float* fng  = (const float*)d_in[27];
    const float* fnb  = (const float*)d_in[28];
    float* out = (float*)d_out;

    const int SM_ATT = 25344 * 4;   // 101376
    const int SM_EE  = 4672 * 4;    // 18688
    const int SM_PQ  = (2176 + 4224) * 4;   // 25600
    const int SM_UPD = (15136 + 4224) * 4;  // 77440
    const int SM_FFN = 15104 * 4;   // 60416
    cudaFuncSetAttribute(attn_kernel,     cudaFuncAttributeMaxDynamicSharedMemorySize, SM_ATT);
    cudaFuncSetAttribute(edge_emb_kernel, cudaFuncAttributeMaxDynamicSharedMemorySize, SM_EE);
    cudaFuncSetAttribute(pq_kernel,       cudaFuncAttributeMaxDynamicSharedMemorySize, SM_PQ);
    cudaFuncSetAttribute(update_kernel,   cudaFuncAttributeMaxDynamicSharedMemorySize, SM_UPD);
    cudaFuncSetAttribute(ffn_kernel,      cudaFuncAttributeMaxDynamicSharedMemorySize, SM_FFN);

    // position 4 gets captured by ncu -> pq (P-only; verifies halved traffic)
    prep_kernel      <<<202, 512>>>(ipw, opw, mw1, mw2, uw1, uw2, fw1, fw2, ew2);
    attn_kernel      <<<2500, 512, SM_ATT>>>(x, ipb, opb, tng, tnb);
    csr_count_kernel <<<79, 256>>>(ei);
    pq_kernel        <<<5000, 512, SM_PQ>>>();
    csr_scan_kernel  <<<1, 1024>>>();
    csr_fill_kernel  <<<79, 256>>>(ei);
    edge_emb_kernel  <<<625, 512, SM_EE>>>(ea, ew1, eb1, eb2, mb1);
    update_kernel    <<<5000, 512, SM_UPD>>>(mb2, ub1, ub2, sng, snb);
    ffn_kernel       <<<5000, 512, SM_FFN>>>(fb1, fb2, fng, fnb, out);
}

// round 17
// speedup vs baseline: 1.2411x; 1.0276x over previous
#include <cuda_runtime.h>

// ---------------- problem constants ----------------
#define BB    2
#define SS    16
#define NN    5000
#define HH    64
#define EE    20000
#define BSS   (BB*SS)      // 32
#define BNN   (BB*NN)      // 10000
#define NROWS (BSS*NN)     // 160000

// ---------------- scratch (device globals) ----------------
__device__ __align__(16) float g_x1[NROWS*HH];
__device__ __align__(16) float g_x2[NROWS*HH];
__device__ __align__(16) float g_P [NROWS*128];
__device__ __align__(16) float g_R [EE*128];
__device__ int  g_cnt[NN];
__device__ int  g_cur[NN];
__device__ int  g_off[NN+1];
__device__ int2 g_epk[EE];     // (src, e) sorted by dst

// fragment-permuted weights (filled once per launch by prep_kernel)
__device__ __align__(16) float g_Wif [12288];   // in_proj 64x192, NT=24
__device__ __align__(16) float g_Wof [4096];    // out_proj 64x64, NT=8
__device__ __align__(16) float g_WPf [8192];    // Wa-Wb 64x128, NT=16 (pq)
__device__ __align__(16) float g_WQf [8192];    // Wb 64x128, NT=16 (update)
__device__ __align__(16) float g_W2f [8192];    // mw2 128x64, NT=8
__device__ __align__(16) float g_U1f [8192];    // uw1 128x64, NT=8
__device__ __align__(16) float g_U2f [4096];    // uw2 64x64, NT=8
__device__ __align__(16) float g_F1f [16384];   // fw1 64x256, NT=32
__device__ __align__(16) float g_F2f [16384];   // fw2 256x64, NT=8
__device__ __align__(16) float g_E2f [4096];    // ew2 64x64, NT=8
__device__ __align__(16) float g_Wcf [8192];    // mw1 rows 128..191 (64x128), NT=16

__device__ __forceinline__ float gelu_f(float v) {
    return 0.5f * v * (1.0f + erff(v * 0.70710678118654752f));
}

__device__ __forceinline__ float to_tf32(float x) {
    unsigned r;
    asm("cvt.rna.tf32.f32 %0, %1;" : "=r"(r) : "f"(x));
    return __uint_as_float(r);
}

__device__ __forceinline__ int fragidx(int k, int c, int NT) {
    int kt = k >> 3, kk = k & 7, j = kk >> 2, tg = kk & 3;
    int nt = c >> 3, gg = c & 7;
    return ((kt*NT + nt)*32 + (gg<<2) + tg)*2 + j;
}

// mma.m16n8k8 tf32: D(16x8) += A(16x8,row) * B(8x8,col)
__device__ __forceinline__ void mma_tf32(float4& d,
    float a0, float a1, float a2, float a3, float b0, float b1)
{
    asm volatile(
      "mma.sync.aligned.m16n8k8.row.col.f32.tf32.tf32.f32 "
      "{%0,%1,%2,%3},{%4,%5,%6,%7},{%8,%9},{%0,%1,%2,%3};\n"
      : "+f"(d.x), "+f"(d.y), "+f"(d.z), "+f"(d.w)
      : "r"(__float_as_uint(a0)), "r"(__float_as_uint(a1)),
        "r"(__float_as_uint(a2)), "r"(__float_as_uint(a3)),
        "r"(__float_as_uint(b0)), "r"(__float_as_uint(b1)));
}

// ---------------- prep: permute weights + zero CSR counters -----------------
__global__ void prep_kernel(
    const float* __restrict__ Wi,  const float* __restrict__ Wo,
    const float* __restrict__ mw1, const float* __restrict__ mw2,
    const float* __restrict__ uw1, const float* __restrict__ uw2,
    const float* __restrict__ fw1, const float* __restrict__ fw2,
    const float* __restrict__ ew2)
{
    int i = blockIdx.x * 512 + threadIdx.x;   // grid 202*512
    if (i < 12288) {                              // Wi 64x192
        int k = i / 192, c = i % 192;
        g_Wif[fragidx(k, c, 24)] = to_tf32(Wi[i]);
    } else if (i < 16384) {                       // Wo 64x64
        int idx = i - 12288, k = idx >> 6, c = idx & 63;
        g_Wof[fragidx(k, c, 8)] = to_tf32(Wo[idx]);
    } else if (i < 24576) {                       // WP = Wa-Wb 64x128
        int idx = i - 16384, k = idx >> 7, c = idx & 127;
        g_WPf[fragidx(k, c, 16)] = to_tf32(mw1[k*128 + c] - mw1[(64+k)*128 + c]);
    } else if (i < 32768) {                       // WQ = Wb 64x128
        int idx = i - 24576, k = idx >> 7, c = idx & 127;
        g_WQf[fragidx(k, c, 16)] = to_tf32(mw1[(64+k)*128 + c]);
    } else if (i < 40960) {                       // mw2 128x64
        int idx = i - 32768, k = idx >> 6, c = idx & 63;
        g_W2f[fragidx(k, c, 8)] = to_tf32(mw2[idx]);
    } else if (i < 49152) {                       // uw1 128x64
        int idx = i - 40960, k = idx >> 6, c = idx & 63;
        g_U1f[fragidx(k, c, 8)] = to_tf32(uw1[idx]);
    } else if (i < 53248) {                       // uw2 64x64
        int idx = i - 49152, k = idx >> 6, c = idx & 63;
        g_U2f[fragidx(k, c, 8)] = to_tf32(uw2[idx]);
    } else if (i < 69632) {                       // fw1 64x256
        int idx = i - 53248, k = idx >> 8, c = idx & 255;
        g_F1f[fragidx(k, c, 32)] = to_tf32(fw1[idx]);
    } else if (i < 86016) {                       // fw2 256x64
        int idx = i - 69632, k = idx >> 6, c = idx & 63;
        g_F2f[fragidx(k, c, 8)] = to_tf32(fw2[idx]);
    } else if (i < 90112) {                       // ew2 64x64
        int idx = i - 86016, k = idx >> 6, c = idx & 63;
        g_E2f[fragidx(k, c, 8)] = to_tf32(ew2[idx]);
    } else if (i < 98304) {                       // Wc = mw1 rows 128..191, 64x128
        int idx = i - 90112, k = idx >> 7, c = idx & 127;
        g_Wcf[fragidx(k, c, 16)] = to_tf32(mw1[(128 + k)*128 + c]);
    } else if (i < 98304 + NN) {                  // zero CSR counters
        g_cnt[i - 98304] = 0;
    }
}

// ---------------- CSR build ----------------
__global__ void csr_count_kernel(const int* __restrict__ ei) {
    int e = blockIdx.x * blockDim.x + threadIdx.x;
    if (e < EE) atomicAdd(&g_cnt[ei[EE + e]], 1);
}
__global__ void csr_scan_kernel() {
    __shared__ int sbuf[1024];
    __shared__ int scarry;
    int t = threadIdx.x;
    if (t == 0) scarry = 0;
    __syncthreads();
    for (int ch = 0; ch < 5; ch++) {
        int idx = ch * 1024 + t;
        int v = (idx < NN) ? g_cnt[idx] : 0;
        sbuf[t] = v; __syncthreads();
        for (int o = 1; o < 1024; o <<= 1) {
            int x = (t >= o) ? sbuf[t - o] : 0;
            __syncthreads();
            sbuf[t] += x;
            __syncthreads();
        }
        int incl = sbuf[t];
        int base = scarry;
        if (idx < NN) { int off = base + incl - v; g_off[idx] = off; g_cur[idx] = off; }
        __syncthreads();
        if (t == 1023) scarry = base + sbuf[1023];
        __syncthreads();
    }
    if (t == 0) g_off[NN] = scarry;
}
__global__ void csr_fill_kernel(const int* __restrict__ ei) {
    int e = blockIdx.x * blockDim.x + threadIdx.x;
    if (e < EE) {
        int dst = ei[EE + e];
        int pos = atomicAdd(&g_cur[dst], 1);
        g_epk[pos] = make_int2(ei[e], e);
    }
}

// ---------------- K1: temporal attention via tf32 MMA + residual + LN -------
__global__ __launch_bounds__(512, 2) void attn_kernel(
    const float* __restrict__ x,
    const float* __restrict__ bi, const float* __restrict__ bo,
    const float* __restrict__ tg_, const float* __restrict__ tb_)
{
    extern __shared__ float sm[];
    float* sbi  = sm;            // 192
    float* sbo  = sbi + 192;     // 64
    float* stg  = sbo + 64;      // 64
    float* stb  = stg + 64;      // 64
    float* sX   = stb + 64;      // 64x68 tf32 (also residual source)
    float* sqkvT= sX + 4352;     // [seq<4][j<192][s<16] pad20 = 15360
    float* saoT = sqkvT + 15360; // [seq<4][d<64][q<16] pad20 = 5120
    float* sY   = sqkvT;         // alias: sqkvT dead after softmax
    float* smean= saoT + 5120;   // 64
    float* sinv = smean + 64;    // 64

    int t = threadIdx.x;
    if (t < 192) sbi[t] = bi[t];
    if (t < 64) { sbo[t] = bo[t]; stg[t] = tg_[t]; stb[t] = tb_[t]; }

    int bn0 = blockIdx.x * 4;
    for (int idx = t; idx < 4096; idx += 512) {
        int row = idx >> 6, c = idx & 63;
        int seq = row >> 4, s = row & 15;
        int bn = bn0 + seq;
        int b = bn / NN, n = bn % NN;
        sX[row*68 + c] = to_tf32(x[((b*SS + s)*NN + n)*HH + c]);
    }
    __syncthreads();

    int w = t >> 5, lane = t & 31, g = lane >> 2, tg = lane & 3;

    // qkv = X @ Wi + bi : M=64, N=192, K=64. warp: mt=w>>2, 6 n-tiles
    {
        int mt = w >> 2, ng = w & 3;
        float4 d[6];
        #pragma unroll
        for (int i = 0; i < 6; i++) {
            int col = (ng*6 + i)*8 + 2*tg;
            d[i] = make_float4(sbi[col], sbi[col+1], sbi[col], sbi[col+1]);
        }
        #pragma unroll
        for (int kt = 0; kt < 8; kt++) {
            const float* Ab = sX + (mt*16)*68 + kt*8;
            float a0 = Ab[g*68 + tg],     a1 = Ab[(g+8)*68 + tg];
            float a2 = Ab[g*68 + tg + 4], a3 = Ab[(g+8)*68 + tg + 4];
            #pragma unroll
            for (int i = 0; i < 6; i++) {
                int nt = ng*6 + i;
                float2 b = __ldg((const float2*)&g_Wif[((kt*24 + nt)*32 + lane)*2]);
                mma_tf32(d[i], a0, a1, a2, a3, b.x, b.y);
            }
        }
        #pragma unroll
        for (int i = 0; i < 6; i++) {
            int col = (ng*6 + i)*8 + 2*tg;
            float* base = sqkvT + (mt*192 + col)*20;
            base[g]        = d[i].x;
            base[20 + g]   = d[i].y;
            base[g + 8]    = d[i].z;
            base[20 + g+8] = d[i].w;
        }
    }
    __syncthreads();

    // attention core (exact fp32): thread = (seq, head, q), 256 active
    if (t < 256) {
        int seq = t >> 6, h = (t >> 4) & 3, q = t & 15;
        const float* Qb = sqkvT + (seq*192 + h*16)*20;
        const float* Kb = Qb + 64*20;
        const float* Vb = Qb + 128*20;
        float sc[16];
        #pragma unroll
        for (int k = 0; k < 16; k++) sc[k] = 0.f;
        #pragma unroll
        for (int d = 0; d < 16; d++) {
            float qv = Qb[d*20 + q];
            const float4* kk = (const float4*)(Kb + d*20);
            float4 k0 = kk[0], k1 = kk[1], k2 = kk[2], k3 = kk[3];
            sc[0]+=qv*k0.x; sc[1]+=qv*k0.y; sc[2]+=qv*k0.z; sc[3]+=qv*k0.w;
            sc[4]+=qv*k1.x; sc[5]+=qv*k1.y; sc[6]+=qv*k1.z; sc[7]+=qv*k1.w;
            sc[8]+=qv*k2.x; sc[9]+=qv*k2.y; sc[10]+=qv*k2.z; sc[11]+=qv*k2.w;
            sc[12]+=qv*k3.x; sc[13]+=qv*k3.y; sc[14]+=qv*k3.z; sc[15]+=qv*k3.w;
        }
        float mx = -1e30f;
        #pragma unroll
        for (int k = 0; k < 16; k++) { sc[k] *= 0.25f; mx = fmaxf(mx, sc[k]); }
        float den = 0.f;
        #pragma unroll
        for (int k = 0; k < 16; k++) { sc[k] = expf(sc[k] - mx); den += sc[k]; }
        float inv = 1.f / den;
        #pragma unroll
        for (int d = 0; d < 16; d++) {
            const float4* vv = (const float4*)(Vb + d*20);
            float4 v0 = vv[0], v1 = vv[1], v2 = vv[2], v3 = vv[3];
            float o = sc[0]*v0.x + sc[1]*v0.y + sc[2]*v0.z + sc[3]*v0.w
                    + sc[4]*v1.x + sc[5]*v1.y + sc[6]*v1.z + sc[7]*v1.w
                    + sc[8]*v2.x + sc[9]*v2.y + sc[10]*v2.z + sc[11]*v2.w
                    + sc[12]*v3.x + sc[13]*v3.y + sc[14]*v3.z + sc[15]*v3.w;
            saoT[(seq*64 + h*16 + d)*20 + q] = to_tf32(o * inv);
        }
    }
    __syncthreads();

    // out-proj: Y = X + AO @ Wo + bo
    {
        int mt = w >> 2, np = w & 3;
        float4 d[2];
        #pragma unroll
        for (int i = 0; i < 2; i++) {
            int col = (np*2 + i)*8 + 2*tg;
            d[i] = make_float4(sbo[col], sbo[col+1], sbo[col], sbo[col+1]);
        }
        #pragma unroll
        for (int kt = 0; kt < 8; kt++) {
            const float* Ab = saoT + (mt*64 + kt*8)*20;
            float a0 = Ab[tg*20 + g],       a1 = Ab[tg*20 + g + 8];
            float a2 = Ab[(tg+4)*20 + g],   a3 = Ab[(tg+4)*20 + g + 8];
            #pragma unroll
            for (int i = 0; i < 2; i++) {
                int nt = np*2 + i;
                float2 b = __ldg((const float2*)&g_Wof[((((kt<<3) + nt)<<5) + lane)*2]);
                mma_tf32(d[i], a0, a1, a2, a3, b.x, b.y);
            }
        }
        int r0 = mt*16 + g;
        #pragma unroll
        for (int i = 0; i < 2; i++) {
            int col = (np*2 + i)*8 + 2*tg;
            sY[r0*64 + col]       = sX[r0*68 + col]       + d[i].x;
            sY[r0*64 + col+1]     = sX[r0*68 + col+1]     + d[i].y;
            sY[(r0+8)*64 + col]   = sX[(r0+8)*68 + col]   + d[i].z;
            sY[(r0+8)*64 + col+1] = sX[(r0+8)*68 + col+1] + d[i].w;
        }
    }
    __syncthreads();

    // LN: 64 rows, 8 lanes per row
    {
        int r = t >> 3, l = t & 7;
        float4 v1 = *(const float4*)&sY[r*64 + l*8];
        float4 v2 = *(const float4*)&sY[r*64 + l*8 + 4];
        float s  = v1.x+v1.y+v1.z+v1.w + v2.x+v2.y+v2.z+v2.w;
        float ss = v1.x*v1.x+v1.y*v1.y+v1.z*v1.z+v1.w*v1.w
                 + v2.x*v2.x+v2.y*v2.y+v2.z*v2.z+v2.w*v2.w;
        #pragma unroll
        for (int o = 1; o < 8; o <<= 1) {
            s  += __shfl_xor_sync(0xffffffffu, s,  o, 8);
            ss += __shfl_xor_sync(0xffffffffu, ss, o, 8);
        }
        if (l == 0) {
            float m = s * (1.f/64.f);
            float var = ss * (1.f/64.f) - m*m;
            smean[r] = m; sinv[r] = rsqrtf(var + 1e-5f);
        }
    }
    __syncthreads();
    for (int idx = t; idx < 4096; idx += 512) {
        int row = idx >> 6, c = idx & 63;
        int seq = row >> 4, s = row & 15;
        int bn = bn0 + seq;
        int b = bn / NN, n = bn % NN;
        g_x1[((b*SS + s)*NN + n)*HH + c] =
            (sY[idx] - smean[row]) * sinv[row] * stg[c] + stb[c];
    }
}

// ---------------- K2: edge embedding -> R via tf32 MMA ----------------------
__global__ __launch_bounds__(512) void edge_emb_kernel(
    const float* __restrict__ ea,
    const float* __restrict__ ew1, const float* __restrict__ eb1,
    const float* __restrict__ eb2, const float* __restrict__ mb1)
{
    extern __shared__ float sm[];
    float* sE0  = sm;          // 32x68 tf32
    float* sE2  = sm + 2176;   // 32x68 tf32
    float* sew1 = sm + 4352;   // 64
    float* seb1 = sew1 + 64;   // 64
    float* seb2 = seb1 + 64;   // 64
    float* smb1 = seb2 + 64;   // 128

    int t = threadIdx.x;
    if (t < 64) { sew1[t] = ew1[t]; seb1[t] = eb1[t]; seb2[t] = eb2[t]; }
    else if (t < 192) smb1[t-64] = mb1[t-64];
    int e0 = blockIdx.x * 32;
    __syncthreads();

    // Stage0: E0 = gelu(ea * ew1 + eb1) per edge-row
    for (int idx = t; idx < 2048; idx += 512) {
        int r = idx >> 6, c = idx & 63;
        sE0[r*68 + c] = to_tf32(gelu_f(__ldg(&ea[e0 + r]) * sew1[c] + seb1[c]));
    }
    __syncthreads();

    int w = t >> 5, lane = t & 31, g = lane >> 2, tg = lane & 3;

    // Stage1: E2 = E0 @ ew2 + eb2 : M=32, N=64, K=64
    {
        int mt = w >> 3, nt = w & 7;
        int col = nt*8 + 2*tg;
        int r0 = mt*16 + g;
        float4 d = make_float4(seb2[col], seb2[col+1], seb2[col], seb2[col+1]);
        #pragma unroll
        for (int kt = 0; kt < 8; kt++) {
            const float* Ab = sE0 + (mt*16)*68 + kt*8;
            float a0 = Ab[g*68 + tg],     a1 = Ab[(g+8)*68 + tg];
            float a2 = Ab[g*68 + tg + 4], a3 = Ab[(g+8)*68 + tg + 4];
            float2 b = __ldg((const float2*)&g_E2f[((((kt<<3) + nt)<<5) + lane)*2]);
            mma_tf32(d, a0, a1, a2, a3, b.x, b.y);
        }
        *(float2*)&sE2[r0*68 + col]     = make_float2(to_tf32(d.x), to_tf32(d.y));
        *(float2*)&sE2[(r0+8)*68 + col] = make_float2(to_tf32(d.z), to_tf32(d.w));
    }
    __syncthreads();

    // Stage2: R = E2 @ Wc + mb1 : M=32, N=128, K=64 (warp does 2 n-tiles)
    {
        int mt = w >> 3, ng = w & 7;
        float4 d[2];
        #pragma unroll
        for (int i = 0; i < 2; i++) {
            int col = (ng*2 + i)*8 + 2*tg;
            d[i] = make_float4(smb1[col], smb1[col+1], smb1[col], smb1[col+1]);
        }
        #pragma unroll
        for (int kt = 0; kt < 8; kt++) {
            const float* Ab = sE2 + (mt*16)*68 + kt*8;
            float a0 = Ab[g*68 + tg],     a1 = Ab[(g+8)*68 + tg];
            float a2 = Ab[g*68 + tg + 4], a3 = Ab[(g+8)*68 + tg + 4];
            #pragma unroll
            for (int i = 0; i < 2; i++) {
                int nt = ng*2 + i;
                float2 b = __ldg((const float2*)&g_Wcf[((kt*16 + nt)*32 + lane)*2]);
                mma_tf32(d[i], a0, a1, a2, a3, b.x, b.y);
            }
        }
        int r0 = mt*16 + g;
        #pragma unroll
        for (int i = 0; i < 2; i++) {
            int col = (ng*2 + i)*8 + 2*tg;
            *(float2*)&g_R[(e0 + r0)*128 + col]     = make_float2(d[i].x, d[i].y);
            *(float2*)&g_R[(e0 + r0 + 8)*128 + col] = make_float2(d[i].z, d[i].w);
        }
    }
}

// ---------------- K3: P node GEMM via tf32 MMA (smem-staged stores) ---------
__global__ __launch_bounds__(512) void pq_kernel()
{
    extern __shared__ float sm[];
    float* sA   = sm;          // 32 x 68 (tf32)
    float* sOut = sm + 2176;   // 32 x 132 (fp32 results, padded)

    int t = threadIdx.x;
    int rbase = blockIdx.x * 32;
    for (int idx = t; idx < 2048; idx += 512) {
        int r = idx >> 6, c = idx & 63;
        sA[r*68 + c] = to_tf32(g_x1[(rbase + r)*64 + c]);
    }
    __syncthreads();

    int w = t >> 5, lane = t & 31, g = lane >> 2, tg = lane & 3;
    int mt = w >> 3, ng = w & 7;
    float4 d[2];
    #pragma unroll
    for (int i = 0; i < 2; i++) d[i] = make_float4(0.f, 0.f, 0.f, 0.f);

    #pragma unroll
    for (int kt = 0; kt < 8; kt++) {
        const float* Ab = sA + (mt*16)*68 + kt*8;
        float a0 = Ab[g*68 + tg],     a1 = Ab[(g+8)*68 + tg];
        float a2 = Ab[g*68 + tg + 4], a3 = Ab[(g+8)*68 + tg + 4];
        #pragma unroll
        for (int i = 0; i < 2; i++) {
            int nt = ng*2 + i;
            float2 b = __ldg((const float2*)&g_WPf[((kt*16 + nt)*32 + lane)*2]);
            mma_tf32(d[i], a0, a1, a2, a3, b.x, b.y);
        }
    }

    {
        int r0 = mt*16 + g;
        #pragma unroll
        for (int i = 0; i < 2; i++) {
            int col = (ng*2 + i)*8 + 2*tg;
            *(float2*)&sOut[r0*132 + col]     = make_float2(d[i].x, d[i].y);
            *(float2*)&sOut[(r0+8)*132 + col] = make_float2(d[i].z, d[i].w);
        }
    }
    __syncthreads();

    for (int idx = t; idx < 4096; idx += 512) {
        int r = idx >> 7, c = idx & 127;
        g_P[(rbase + r)*128 + c] = sOut[r*132 + c];
    }
}

// ---------------- K5: fused Q-GEMM + gather + update MLP + LN ---------------
__global__ __launch_bounds__(512) void update_kernel(
    const float* __restrict__ mb2, const float* __restrict__ ub1,
    const float* __restrict__ ub2,
    const float* __restrict__ sg,  const float* __restrict__ sb)
{
    extern __shared__ float sm[];
    float* sG   = sm;               // 32 x 132 tf32
    float* sUin = sG + 4224;        // 32 x 132 tf32
    float* sHid = sUin + 4224;      // 32 x 68 tf32
    float* sXr  = sHid + 2176;      // 32 x 64 fp32
    float* sY   = sXr + 2048;       // 32 x 64
    float* smb2 = sY + 2048;        // 64
    float* sub1 = smb2 + 64;
    float* sub2 = sub1 + 64;
    float* ssg  = sub2 + 64;
    float* ssb  = ssg + 64;
    float* sdeg = ssb + 64;         // 32
    float* smean= sdeg + 32;        // 32
    float* sinv = smean + 32;       // 32
    float* sQ   = sinv + 32;        // 32 x 132 fp32 (4224)

    int t = threadIdx.x;
    if (t < 64) { smb2[t] = mb2[t]; sub1[t] = ub1[t]; sub2[t] = ub2[t]; ssg[t] = sg[t]; ssb[t] = sb[t]; }

    int rbase = blockIdx.x * 32;
    for (int idx = t; idx < 2048; idx += 512) {
        int c = idx & 63, r = idx >> 6;
        float v = g_x1[(rbase + r)*64 + c];
        sXr[r*64 + c] = v;
        sUin[r*132 + c] = to_tf32(v);
    }
    __syncthreads();

    int w = t >> 5, lane = t & 31;
    int g = lane >> 2, tg = lane & 3;

    // Stage Q: Q = X @ Wb : M=32, N=128, K=64 (warp does 2 n-tiles)
    {
        int mt = w >> 3, ng = w & 7;
        float4 d[2];
        #pragma unroll
        for (int i = 0; i < 2; i++) d[i] = make_float4(0.f, 0.f, 0.f, 0.f);
        #pragma unroll
        for (int kt = 0; kt < 8; kt++) {
            const float* Ab = sUin + (mt*16)*132 + kt*8;
            float a0 = Ab[g*132 + tg],     a1 = Ab[(g+8)*132 + tg];
            float a2 = Ab[g*132 + tg + 4], a3 = Ab[(g+8)*132 + tg + 4];
            #pragma unroll
            for (int i = 0; i < 2; i++) {
                int nt = ng*2 + i;
                float2 b = __ldg((const float2*)&g_WQf[((kt*16 + nt)*32 + lane)*2]);
                mma_tf32(d[i], a0, a1, a2, a3, b.x, b.y);
            }
        }
        int r0 = mt*16 + g;
        #pragma unroll
        for (int i = 0; i < 2; i++) {
            int col = (ng*2 + i)*8 + 2*tg;
            *(float2*)&sQ[r0*132 + col]     = make_float2(d[i].x, d[i].y);
            *(float2*)&sQ[(r0+8)*132 + col] = make_float2(d[i].z, d[i].w);
        }
    }
    __syncthreads();

    // fused CSR gather: warp w accumulates rows w*2, w*2+1 into sG (tf32)
    {
        const float4* P4 = (const float4*)g_P;
        const float4* R4 = (const float4*)g_R;
        #pragma unroll
        for (int j = 0; j < 2; j++) {
            int lr = w*2 + j;                 // local row 0..31
            int row = rbase + lr;
            int bs = row / NN, n = row - bs*NN;
            float4 q = *(const float4*)&sQ[lr*132 + lane*4];
            float4 acc = make_float4(0.f, 0.f, 0.f, 0.f);
            int s = __ldg(&g_off[n]), e = __ldg(&g_off[n+1]);
            if (s < e) {
                int2 pe = __ldg(&g_epk[s]);
                for (int k = s; k < e; k++) {
                    int2 pen = (k + 1 < e) ? __ldg(&g_epk[k+1]) : pe;
                    float4 p = __ldg(P4 + (bs*NN + pe.x)*32 + lane);
                    float4 r = __ldg(R4 + pe.y*32 + lane);
                    acc.x += gelu_f(p.x + q.x + r.x);
                    acc.y += gelu_f(p.y + q.y + r.y);
                    acc.z += gelu_f(p.z + q.z + r.z);
                    acc.w += gelu_f(p.w + q.w + r.w);
                    pe = pen;
                }
            }
            *(float4*)&sG[lr*132 + lane*4] =
                make_float4(to_tf32(acc.x), to_tf32(acc.y),
                            to_tf32(acc.z), to_tf32(acc.w));
            if (lane == 0) sdeg[lr] = (float)(e - s);
        }
    }
    __syncthreads();

    int mt = w >> 3, nt = w & 7;
    int col = nt*8 + 2*tg;
    int r0 = mt*16 + g;

    // Stage0: aggr = G @ mw2 + deg*mb2
    {
        float4 d = make_float4(sdeg[r0]*smb2[col],   sdeg[r0]*smb2[col+1],
                               sdeg[r0+8]*smb2[col], sdeg[r0+8]*smb2[col+1]);
        #pragma unroll
        for (int kt = 0; kt < 16; kt++) {
            const float* Ab = sG + (mt*16)*132 + kt*8;
            float a0 = Ab[g*132 + tg],     a1 = Ab[(g+8)*132 + tg];
            float a2 = Ab[g*132 + tg + 4], a3 = Ab[(g+8)*132 + tg + 4];
            float2 b = __ldg((const float2*)&g_W2f[((((kt<<3) + nt)<<5) + lane)*2]);
            mma_tf32(d, a0, a1, a2, a3, b.x, b.y);
        }
        *(float2*)&sUin[r0*132 + 64 + col]     = make_float2(to_tf32(d.x), to_tf32(d.y));
        *(float2*)&sUin[(r0+8)*132 + 64 + col] = make_float2(to_tf32(d.z), to_tf32(d.w));
    }
    __syncthreads();

    // Stage1: hid = gelu(Uin @ uw1 + ub1)
    {
        float4 d = make_float4(sub1[col], sub1[col+1], sub1[col], sub1[col+1]);
        #pragma unroll
        for (int kt = 0; kt < 16; kt++) {
            const float* Ab = sUin + (mt*16)*132 + kt*8;
            float a0 = Ab[g*132 + tg],     a1 = Ab[(g+8)*132 + tg];
            float a2 = Ab[g*132 + tg + 4], a3 = Ab[(g+8)*132 + tg + 4];
            float2 b = __ldg((const float2*)&g_U1f[((((kt<<3) + nt)<<5) + lane)*2]);
            mma_tf32(d, a0, a1, a2, a3, b.x, b.y);
        }
        *(float2*)&sHid[r0*68 + col]     = make_float2(to_tf32(gelu_f(d.x)), to_tf32(gelu_f(d.y)));
        *(float2*)&sHid[(r0+8)*68 + col] = make_float2(to_tf32(gelu_f(d.z)), to_tf32(gelu_f(d.w)));
    }
    __syncthreads();

    // Stage2: y = xs + hid @ uw2 + ub2
    {
        float4 d = make_float4(sub2[col], sub2[col+1], sub2[col], sub2[col+1]);
        #pragma unroll
        for (int kt = 0; kt < 8; kt++) {
            const float* Ab = sHid + (mt*16)*68 + kt*8;
            float a0 = Ab[g*68 + tg],     a1 = Ab[(g+8)*68 + tg];
            float a2 = Ab[g*68 + tg + 4], a3 = Ab[(g+8)*68 + tg + 4];
            float2 b = __ldg((const float2*)&g_U2f[((((kt<<3) + nt)<<5) + lane)*2]);
            mma_tf32(d, a0, a1, a2, a3, b.x, b.y);
        }
        sY[r0*64 + col]       = sXr[r0*64 + col]       + d.x;
        sY[r0*64 + col+1]     = sXr[r0*64 + col+1]     + d.y;
        sY[(r0+8)*64 + col]   = sXr[(r0+8)*64 + col]   + d.z;
        sY[(r0+8)*64 + col+1] = sXr[(r0+8)*64 + col+1] + d.w;
    }
    __syncthreads();

    // LN
    {
        int r = t >> 4, l = t & 15;
        float4 v = *(const float4*)&sY[r*64 + l*4];
        float s  = v.x + v.y + v.z + v.w;
        float ss = v.x*v.x + v.y*v.y + v.z*v.z + v.w*v.w;
        #pragma unroll
        for (int o = 1; o < 16; o <<= 1) {
            s  += __shfl_xor_sync(0xffffffffu, s,  o, 16);
            ss += __shfl_xor_sync(0xffffffffu, ss, o, 16);
        }
        if (l == 0) {
            float m = s * (1.f/64.f);
            float var = ss * (1.f/64.f) - m*m;
            smean[r] = m; sinv[r] = rsqrtf(var + 1e-5f);
        }
    }
    __syncthreads();
    for (int i = t; i < 2048; i += 512) {
        int r = i >> 6, cc = i & 63;
        g_x2[(rbase + r)*64 + cc] = (sY[i] - smean[r]) * sinv[r] * ssg[cc] + ssb[cc];
    }
}

// ---------------- K6: FFN via tf32 MMA + residual + LN -> d_out --------------
__global__ __launch_bounds__(512) void ffn_kernel(
    const float* __restrict__ fb1, const float* __restrict__ fb2,
    const float* __restrict__ fg,  const float* __restrict__ fb,
    float* __restrict__ out)
{
    extern __shared__ float sm[];
    float* sA   = sm;               // X 32 x 68 tf32
    float* sH   = sA + 2176;        // H 32 x 260 tf32
    float* sXr  = sH + 8320;        // 32 x 64 fp32
    float* sY   = sXr + 2048;       // 32 x 64
    float* sb1  = sY + 2048;        // 256
    float* sb2  = sb1 + 256;        // 64
    float* sfg  = sb2 + 64;
    float* sfb  = sfg + 64;
    float* smean= sfb + 64;         // 32
    float* sinv = smean + 32;       // 32

    int t = threadIdx.x;
    if (t < 256) sb1[t] = fb1[t];
    if (t < 64) { sb2[t] = fb2[t]; sfg[t] = fg[t]; sfb[t] = fb[t]; }

    int rbase = blockIdx.x * 32;
    for (int idx = t; idx < 2048; idx += 512) {
        int c = idx & 63, r = idx >> 6;
        float v = g_x2[(rbase + r)*64 + c];
        sXr[r*64 + c] = v;
        sA[r*68 + c] = to_tf32(v);
    }
    __syncthreads();

    int w = t >> 5, lane = t & 31, g = lane >> 2, tg = lane & 3;

    // Stage1: H = gelu(X @ W1 + b1)
    {
        int mt = w >> 3, ng = w & 7;
        float4 d[4];
        #pragma unroll
        for (int i = 0; i < 4; i++) {
            int col = (ng*4 + i)*8 + 2*tg;
            d[i] = make_float4(sb1[col], sb1[col+1], sb1[col], sb1[col+1]);
        }
        #pragma unroll
        for (int kt = 0; kt < 8; kt++) {
            const float* Ab = sA + (mt*16)*68 + kt*8;
            float a0 = Ab[g*68 + tg],     a1 = Ab[(g+8)*68 + tg];
            float a2 = Ab[g*68 + tg + 4], a3 = Ab[(g+8)*68 + tg + 4];
            #pragma unroll
            for (int i = 0; i < 4; i++) {
                int nt = ng*4 + i;
                float2 b = __ldg((const float2*)&g_F1f[((((kt<<5) + nt)<<5) + lane)*2]);
                mma_tf32(d[i], a0, a1, a2, a3, b.x, b.y);
            }
        }
        int r0 = mt*16 + g;
        #pragma unroll
        for (int i = 0; i < 4; i++) {
            int col = (ng*4 + i)*8 + 2*tg;
            *(float2*)&sH[r0*260 + col]     = make_float2(to_tf32(gelu_f(d[i].x)), to_tf32(gelu_f(d[i].y)));
            *(float2*)&sH[(r0+8)*260 + col] = make_float2(to_tf32(gelu_f(d[i].z)), to_tf32(gelu_f(d[i].w)));
        }
    }
    __syncthreads();

    // Stage2: Y = X + H @ W2 + b2
    {
        int mt = w >> 3, nt = w & 7;
        int col = nt*8 + 2*tg;
        int r0 = mt*16 + g;
        float4 d = make_float4(sb2[col], sb2[col+1], sb2[col], sb2[col+1]);
        #pragma unroll
        for (int kt = 0; kt < 32; kt++) {
            const float* Ab = sH + (mt*16)*260 + kt*8;
            float a0 = Ab[g*260 + tg],     a1 = Ab[(g+8)*260 + tg];
            float a2 = Ab[g*260 + tg + 4], a3 = Ab[(g+8)*260 + tg + 4];
            float2 b = __ldg((const float2*)&g_F2f[((((kt<<3) + nt)<<5) + lane)*2]);
            mma_tf32(d, a0, a1, a2, a3, b.x, b.y);
        }
        sY[r0*64 + col]       = sXr[r0*64 + col]       + d.x;
        sY[r0*64 + col+1]     = sXr[r0*64 + col+1]     + d.y;
        sY[(r0+8)*64 + col]   = sXr[(r0+8)*64 + col]   + d.z;
        sY[(r0+8)*64 + col+1] = sXr[(r0+8)*64 + col+1] + d.w;
    }
    __syncthreads();

    // LN
    {
        int r = t >> 4, l = t & 15;
        float4 v = *(const float4*)&sY[r*64 + l*4];
        float s  = v.x + v.y + v.z + v.w;
        float ss = v.x*v.x + v.y*v.y + v.z*v.z + v.w*v.w;
        #pragma unroll
        for (int o = 1; o < 16; o <<= 1) {
            s  += __shfl_xor_sync(0xffffffffu, s,  o, 16);
            ss += __shfl_xor_sync(0xffffffffu, ss, o, 16);
        }
        if (l == 0) {
            float m = s * (1.f/64.f);
            float var = ss * (1.f/64.f) - m*m;
            smean[r] = m; sinv[r] = rsqrtf(var + 1e-5f);
        }
    }
    __syncthreads();
    for (int i = t; i < 2048; i += 512) {
        int r = i >> 6, cc = i & 63;
        out[(rbase + r)*64 + cc] = (sY[i] - smean[r]) * sinv[r] * sfg[cc] + sfb[cc];
    }
}

// ---------------- host launcher ---------------------------------------------
extern "C" void kernel_launch(void* const* d_in, const int* in_sizes, int n_in,
                              void* d_out, int out_size)
{
    (void)in_sizes; (void)n_in; (void)out_size;
    const float* x    = (const float*)d_in[0];
    const int*   ei   = (const int*)  d_in[1];
    const float* ea   = (const float*)d_in[2];
    const float* ipw  = (const float*)d_in[3];
    const float* ipb  = (const float*)d_in[4];
    const float* opw  = (const float*)d_in[5];
    const float* opb  = (const float*)d_in[6];
    const float* tng  = (const float*)d_in[7];
    const float* tnb  = (const float*)d_in[8];
    const float* ew1  = (const float*)d_in[9];
    const float* eb1  = (const float*)d_in[10];
    const float* ew2  = (const float*)d_in[11];
    const float* eb2  = (const float*)d_in[12];
    const float* mw1  = (const float*)d_in[13];
    const float* mb1  = (const float*)d_in[14];
    const float* mw2  = (const float*)d_in[15];
    const float* mb2  = (const float*)d_in[16];
    const float* uw1  = (const float*)d_in[17];
    const float* ub1  = (const float*)d_in[18];
    const float* uw2  = (const float*)d_in[19];
    const float* ub2  = (const float*)d_in[20];
    const float* sng  = (const float*)d_in[21];
    const float* snb  = (const float*)d_in[22];
    const float* fw1  = (const float*)d_in[23];
    const float* fb1  = (const float*)d_in[24];
    const float* fw2  = (const float*)d_in[25];
    const float* fb2  = (const float*)d_in[26];
    const float* fng  = (const float*)d_in[27];
    const float* fnb  = (const float*)d_in[28];
    float* out = (float*)d_out;

    const int SM_ATT = 25344 * 4;   // 101376
    const int SM_EE  = 4672 * 4;    // 18688
    const int SM_PQ  = (2176 + 4224) * 4;   // 25600
    const int SM_UPD = (15136 + 4224) * 4;  // 77440
    const int SM_FFN = 15104 * 4;   // 60416
    cudaFuncSetAttribute(attn_kernel,     cudaFuncAttributeMaxDynamicSharedMemorySize, SM_ATT);
    cudaFuncSetAttribute(edge_emb_kernel, cudaFuncAttributeMaxDynamicSharedMemorySize, SM_EE);
    cudaFuncSetAttribute(pq_kernel,       cudaFuncAttributeMaxDynamicSharedMemorySize, SM_PQ);
    cudaFuncSetAttribute(update_kernel,   cudaFuncAttributeMaxDynamicSharedMemorySize, SM_UPD);
    cudaFuncSetAttribute(ffn_kernel,      cudaFuncAttributeMaxDynamicSharedMemorySize, SM_FFN);

    // fork/join: branch B (csr + edge_emb) overlaps branch A (attn + pq).
    cudaStream_t s2;
    cudaStreamCreate(&s2);
    cudaEvent_t evFork, evJoin;
    cudaEventCreateWithFlags(&evFork, cudaEventDisableTiming);
    cudaEventCreateWithFlags(&evJoin, cudaEventDisableTiming);

    prep_kernel      <<<202, 512>>>(ipw, opw, mw1, mw2, uw1, uw2, fw1, fw2, ew2);
    cudaEventRecord(evFork, 0);
    cudaStreamWaitEvent(s2, evFork, 0);

    csr_count_kernel <<<79, 256, 0, s2>>>(ei);
    csr_scan_kernel  <<<1, 1024, 0, s2>>>();
    attn_kernel      <<<2500, 512, SM_ATT>>>(x, ipb, opb, tng, tnb);   // 4th launch -> profiled
    csr_fill_kernel  <<<79, 256, 0, s2>>>(ei);
    edge_emb_kernel  <<<625, 512, SM_EE, s2>>>(ea, ew1, eb1, eb2, mb1);
    pq_kernel        <<<5000, 512, SM_PQ>>>();

    cudaEventRecord(evJoin, s2);
    cudaStreamWaitEvent(0, evJoin, 0);

    update_kernel    <<<5000, 512, SM_UPD>>>(mb2, ub1, ub2, sng, snb);
    ffn_kernel       <<<5000, 512, SM_FFN>>>(fb1, fb2, fng, fnb, out);
    // stream/events intentionally not destroyed: kernel_launch is invoked only
    // a handful of times (correctness + capture); destroying mid-capture is UB.
}